// round 7
// baseline (speedup 1.0000x reference)
#include <cuda_runtime.h>
#include <cstdint>
#include <math.h>

#define HH 128
#define WW 128
#define HWP 16384
#define BATCH 4
#define KIDS 20

// ---------------- scratch (device globals; no allocation) ----------------
__device__ float g_buf1[BATCH * 256 * HWP];   // 67 MB
__device__ float g_buf2[BATCH * 128 * HWP];   // 33.5 MB
__device__ float g_buf3[BATCH * 64 * HWP];    // 16.8 MB
__device__ float g_mr[64];                    // mean/rstd pairs
__device__ float g_gnpart[4096];              // GN partial sums
__device__ float g_partial[BATCH * 32 * KIDS * 64];
__device__ float g_pcnt[BATCH * 32 * KIDS];

// ---------------- tf32 helpers ----------------
__device__ __forceinline__ uint32_t f2tf32(float x) {
    uint32_t r;
    asm("cvt.rna.tf32.f32 %0, %1;" : "=r"(r) : "f"(x));
    return r;
}
__device__ __forceinline__ void mma_tf32(float* c, uint32_t a0, uint32_t a1,
                                         uint32_t a2, uint32_t a3,
                                         uint32_t b0, uint32_t b1) {
    asm volatile("mma.sync.aligned.m16n8k8.row.col.f32.tf32.tf32.f32 "
                 "{%0,%1,%2,%3}, {%4,%5,%6,%7}, {%8,%9}, {%0,%1,%2,%3};"
                 : "+f"(c[0]), "+f"(c[1]), "+f"(c[2]), "+f"(c[3])
                 : "r"(a0), "r"(a1), "r"(a2), "r"(a3), "r"(b0), "r"(b1));
}

// ---------------- conv as tf32 mma.sync implicit GEMM ----------------
// EXACT round-4 passing kernel, with ONE transport-only change: the B
// (im2col) element values for chunk n+1 are computed into registers during
// chunk n's mma (prefetch) and stored to the SAME smem positions with the
// SAME values as round 4. Numerics are bit-identical to round 4.
template<int CI, int CO, bool GN>
__global__ __launch_bounds__(256, 2)
void conv_mma_kernel(const float* __restrict__ in, const float* __restrict__ wgt,
                     const float* __restrict__ bias, float* __restrict__ out,
                     const float* __restrict__ mr, const float* __restrict__ gw,
                     const float* __restrict__ gb, int Gin)
{
    constexpr int K = CI * 9;
    constexpr int NCHUNK = K / 32;
    constexpr int M = (CO < 128) ? CO : 128;  // M tile (rows of A staged)
    constexpr int MFRAG = M / 32;             // 16-row frags per warp (M/2/16)
    constexpr int SB = 34;                    // smem row stride in floats

    extern __shared__ char smem[];
    float* As = reinterpret_cast<float*>(smem);                   // [M][SB]
    float* Bs = As + M * SB;                                      // [128][SB]
    float* scp = Bs + 128 * SB;                                   // GN scale [CI]
    float* shp = scp + (GN ? CI : 0);                             // GN shift [CI]

    const int tile = blockIdx.x;
    const int b = tile >> 7;
    const int y = tile & 127;
    const int m0 = blockIdx.y * M;
    const int tid = threadIdx.x;
    const int w = tid >> 5;
    const int lane = tid & 31;
    const int g = lane >> 2;      // 0..7
    const int q = lane & 3;       // 0..3
    const int warpM = w >> 2;     // 0..1
    const int warpN = w & 3;      // 0..3
    const int m0w = warpM * (M / 2);
    const int n0w = warpN * 32;

    if (GN) {
        const int CPG = CI / Gin;
        for (int c = tid; c < CI; c += 256) {
            int gi = c / CPG;
            float mean = mr[(b * Gin + gi) * 2 + 0];
            float rstd = mr[(b * Gin + gi) * 2 + 1];
            float s = rstd * gw[c];
            scp[c] = s;
            shp[c] = gb[c] - mean * s;
        }
        __syncthreads();   // scp/shp visible before the first B prefetch
    }

    const float* inB = in + (size_t)b * CI * HWP;
    const int px = tid & 127;
    const int khalf = tid >> 7;

    // B prefetch registers: values identical to round-4's in-place staging.
    float bR[16];
    auto loadB_regs = [&](int chunk) {
        const int kbase = chunk * 32;
#pragma unroll
        for (int j = 0; j < 16; j++) {
            int kk = khalf * 16 + j;
            int k = kbase + kk;
            int ci = k / 9;
            int t9 = k - ci * 9;
            int dy = t9 / 3;
            int dx = t9 - dy * 3;
            int yy = y + dy - 1;
            int xx = px + dx - 1;
            float v = 0.f;
            if ((unsigned)yy < 128u && (unsigned)xx < 128u) {
                v = inB[(ci * HH + yy) * WW + xx];
                if (GN) v = fmaxf(fmaf(v, scp[ci], shp[ci]), 0.f);
            }
            bR[j] = __uint_as_float(f2tf32(v));
        }
    };

    float acc[MFRAG][4][4];
#pragma unroll
    for (int mi = 0; mi < MFRAG; mi++)
#pragma unroll
        for (int ni = 0; ni < 4; ni++)
#pragma unroll
            for (int j = 0; j < 4; j++) acc[mi][ni][j] = 0.f;

    loadB_regs(0);

    for (int chunk = 0; chunk < NCHUNK; chunk++) {
        const int kbase = chunk * 32;
        __syncthreads();     // previous compute done before overwrite

        // ---- stage A (weights): verbatim round 4
        for (int idx = tid; idx < M * 8; idx += 256) {
            int row = idx >> 3;
            int c4 = (idx & 7) * 4;
            float4 v = *reinterpret_cast<const float4*>(
                wgt + (size_t)(m0 + row) * K + kbase + c4);
            float* dst = As + row * SB + (c4 >> 2);
            dst[0]  = __uint_as_float(f2tf32(v.x));
            dst[8]  = __uint_as_float(f2tf32(v.y));
            dst[16] = __uint_as_float(f2tf32(v.z));
            dst[24] = __uint_as_float(f2tf32(v.w));
        }
        // ---- stage B from prefetched regs: same positions/values as round 4
#pragma unroll
        for (int j = 0; j < 16; j++) {
            int kk = khalf * 16 + j;
            Bs[px * SB + (kk & 3) * 8 + (kk >> 2)] = bR[j];
        }
        __syncthreads();

        if (chunk + 1 < NCHUNK)     // prefetch next chunk's B during compute
            loadB_regs(chunk + 1);

        // ---- compute: verbatim round 4 (4 k-steps of m16n8k8)
#pragma unroll
        for (int ks = 0; ks < 4; ks++) {
            uint32_t af[MFRAG][4];
#pragma unroll
            for (int mi = 0; mi < MFRAG; mi++) {
                int row = m0w + mi * 16 + g;
                float2 lo = *reinterpret_cast<const float2*>(As + row * SB + q * 8 + 2 * ks);
                float2 hi = *reinterpret_cast<const float2*>(As + (row + 8) * SB + q * 8 + 2 * ks);
                af[mi][0] = __float_as_uint(lo.x);
                af[mi][1] = __float_as_uint(hi.x);
                af[mi][2] = __float_as_uint(lo.y);
                af[mi][3] = __float_as_uint(hi.y);
            }
#pragma unroll
            for (int ni = 0; ni < 4; ni++) {
                int pxn = n0w + ni * 8 + g;
                float2 vb = *reinterpret_cast<const float2*>(Bs + pxn * SB + q * 8 + 2 * ks);
                uint32_t b0 = __float_as_uint(vb.x);
                uint32_t b1 = __float_as_uint(vb.y);
#pragma unroll
                for (int mi = 0; mi < MFRAG; mi++)
                    mma_tf32(acc[mi][ni], af[mi][0], af[mi][1], af[mi][2], af[mi][3], b0, b1);
            }
        }
    }

    // ---- epilogue: verbatim round 4
#pragma unroll
    for (int mi = 0; mi < MFRAG; mi++) {
        int colo = m0 + m0w + mi * 16 + g;
        int cohi = colo + 8;
        float blo = bias[colo];
        float bhi = bias[cohi];
        float* dlo = out + (((size_t)(b * CO + colo)) * HH + y) * WW;
        float* dhi = out + (((size_t)(b * CO + cohi)) * HH + y) * WW;
#pragma unroll
        for (int ni = 0; ni < 4; ni++) {
            int x0 = n0w + ni * 8 + 2 * q;
            float2 v0 = make_float2(acc[mi][ni][0] + blo, acc[mi][ni][1] + blo);
            float2 v1 = make_float2(acc[mi][ni][2] + bhi, acc[mi][ni][3] + bhi);
            *reinterpret_cast<float2*>(dlo + x0) = v0;
            *reinterpret_cast<float2*>(dhi + x0) = v1;
        }
    }
}

// ---------------- GroupNorm statistics: partial pass ----------------
__global__ void gn_part_kernel(const float* __restrict__ x, float* __restrict__ part,
                               int Cg, int SL)
{
    const int bg = blockIdx.x / SL;
    const int sl = blockIdx.x % SL;
    const size_t n = (size_t)Cg * HWP;
    const size_t cn = n / SL;
    const float4* p = reinterpret_cast<const float4*>(x + (size_t)bg * n + (size_t)sl * cn);
    const int n4 = (int)(cn >> 2);

    float s = 0.f, ss = 0.f;
    for (int i = threadIdx.x; i < n4; i += 256) {
        float4 v = p[i];
        s  += v.x + v.y + v.z + v.w;
        ss += v.x * v.x + v.y * v.y + v.z * v.z + v.w * v.w;
    }
    __shared__ float sh_s[256], sh_ss[256];
    sh_s[threadIdx.x] = s;
    sh_ss[threadIdx.x] = ss;
    __syncthreads();
    for (int st = 128; st > 0; st >>= 1) {
        if ((int)threadIdx.x < st) {
            sh_s[threadIdx.x]  += sh_s[threadIdx.x + st];
            sh_ss[threadIdx.x] += sh_ss[threadIdx.x + st];
        }
        __syncthreads();
    }
    if (threadIdx.x == 0) {
        part[blockIdx.x * 2 + 0] = sh_s[0];
        part[blockIdx.x * 2 + 1] = sh_ss[0];
    }
}

// ---------------- GroupNorm statistics: final reduce ----------------
__global__ void gn_final_kernel(const float* __restrict__ part, float* __restrict__ mr,
                                int SL, float inv_n)
{
    const int bg = threadIdx.x;
    float s = 0.f, ss = 0.f;
    for (int i = 0; i < SL; i++) {
        s  += part[(bg * SL + i) * 2 + 0];
        ss += part[(bg * SL + i) * 2 + 1];
    }
    float mean = s * inv_n;
    float var = ss * inv_n - mean * mean;
    mr[bg * 2 + 0] = mean;
    mr[bg * 2 + 1] = rsqrtf(var + 1e-5f);
}

// ---------------- masked segment pooling (GN3+ReLU fused at read) ----------------
__global__ void pool_acc_kernel(const float* __restrict__ h, const int* __restrict__ masks,
                                const float* __restrict__ mr, const float* __restrict__ gw,
                                const float* __restrict__ gb,
                                float* __restrict__ partial, float* __restrict__ pcnt)
{
    const int b = blockIdx.y;
    const int chunk = blockIdx.x;
    const int tid = threadIdx.x;

    __shared__ float s_sums[KIDS * 65];
    __shared__ float s_cnt[KIDS];
    __shared__ float sc[64], sh[64];
    for (int i = tid; i < KIDS * 65; i += 256) s_sums[i] = 0.f;
    if (tid < KIDS) s_cnt[tid] = 0.f;
    if (tid < 64) {
        int g = tid >> 4;
        float mean = mr[(b * 4 + g) * 2 + 0];
        float rstd = mr[(b * 4 + g) * 2 + 1];
        float s = rstd * gw[tid];
        sc[tid] = s;
        sh[tid] = gb[tid] - mean * s;
    }
    __syncthreads();

    const float* hb = h + (size_t)b * 64 * HWP;
    const int* mb = masks + b * HWP;

    const int p0 = chunk * 512;
    for (int p = p0 + tid; p < p0 + 512; p += 256) {
        int k = mb[p] - 1;
        if (k >= 0) {
            atomicAdd(&s_cnt[k], 1.f);
#pragma unroll
            for (int c = 0; c < 64; c++) {
                float v = fmaxf(fmaf(hb[c * HWP + p], sc[c], sh[c]), 0.f);
                atomicAdd(&s_sums[k * 65 + c], v);
            }
        }
    }
    __syncthreads();

    float* pb = partial + (size_t)(b * 32 + chunk) * (KIDS * 64);
    for (int i = tid; i < KIDS * 64; i += 256) {
        int k = i >> 6, c = i & 63;
        pb[i] = s_sums[k * 65 + c];
    }
    if (tid < KIDS) pcnt[(b * 32 + chunk) * KIDS + tid] = s_cnt[tid];
}

// ---------------- reduce partials + dense heads ----------------
__global__ void heads_kernel(const float* __restrict__ partial, const float* __restrict__ pcnt,
                             const float* __restrict__ wb, const float* __restrict__ bb,
                             const float* __restrict__ wc, const float* __restrict__ bc,
                             float* __restrict__ out)
{
    const int b = blockIdx.x;
    const int k = blockIdx.y;
    const int c = threadIdx.x;

    float s = 0.f;
    for (int ch = 0; ch < 32; ch++)
        s += partial[(size_t)(b * 32 + ch) * (KIDS * 64) + k * 64 + c];
    float cnt = 0.f;
    for (int ch = 0; ch < 32; ch++)
        cnt += pcnt[(b * 32 + ch) * KIDS + k];
    float pooled = s / (cnt + 1e-6f);

    __shared__ float red[64];
#pragma unroll
    for (int o = 0; o < 7; o++) {
        red[c] = pooled * wb[o * 64 + c];
        __syncthreads();
        for (int st = 32; st > 0; st >>= 1) {
            if (c < st) red[c] += red[c + st];
            __syncthreads();
        }
        if (c == 0) out[(b * KIDS + k) * 7 + o] = red[0] + bb[o];
        __syncthreads();
    }
    red[c] = pooled * wc[c];
    __syncthreads();
    for (int st = 32; st > 0; st >>= 1) {
        if (c < st) red[c] += red[c + st];
        __syncthreads();
    }
    if (c == 0) {
        float z = red[0] + bc[0];
        out[BATCH * KIDS * 7 + b * KIDS + k] = 1.f / (1.f + expf(-z));
    }
}

// ---------------- launch ----------------
extern "C" void kernel_launch(void* const* d_in, const int* in_sizes, int n_in,
                              void* d_out, int out_size)
{
    const float* x    = (const float*)d_in[0];
    const int*   masks= (const int*)  d_in[1];
    const float* w1   = (const float*)d_in[2];
    const float* b1   = (const float*)d_in[3];
    const float* g1w  = (const float*)d_in[4];
    const float* g1b  = (const float*)d_in[5];
    const float* w2   = (const float*)d_in[6];
    const float* b2   = (const float*)d_in[7];
    const float* g2w  = (const float*)d_in[8];
    const float* g2b  = (const float*)d_in[9];
    const float* w3   = (const float*)d_in[10];
    const float* b3   = (const float*)d_in[11];
    const float* g3w  = (const float*)d_in[12];
    const float* g3b  = (const float*)d_in[13];
    const float* wb   = (const float*)d_in[14];
    const float* bb   = (const float*)d_in[15];
    const float* wc   = (const float*)d_in[16];
    const float* bc   = (const float*)d_in[17];
    float* out = (float*)d_out;

    float *buf1, *buf2, *buf3, *mr, *gnpart, *partial, *pcnt;
    cudaGetSymbolAddress((void**)&buf1, g_buf1);
    cudaGetSymbolAddress((void**)&buf2, g_buf2);
    cudaGetSymbolAddress((void**)&buf3, g_buf3);
    cudaGetSymbolAddress((void**)&mr, g_mr);
    cudaGetSymbolAddress((void**)&gnpart, g_gnpart);
    cudaGetSymbolAddress((void**)&partial, g_partial);
    cudaGetSymbolAddress((void**)&pcnt, g_pcnt);

    // dynamic smem: (M + 128) * 34 * 4 + GN arrays (same as round 4)
    const int SM1 = (128 + 128) * 34 * 4;                 // 34816
    const int SM2 = (128 + 128) * 34 * 4 + 2 * 256 * 4;   // 36864
    const int SM3 = (64 + 128) * 34 * 4 + 2 * 128 * 4;    // 27136

    // layer 1: 512 -> 256
    conv_mma_kernel<512, 256, false><<<dim3(512, 2), 256, SM1>>>(
        x, w1, b1, buf1, nullptr, nullptr, nullptr, 0);
    gn_part_kernel<<<32 * 16, 256>>>(buf1, gnpart, 32, 16);
    gn_final_kernel<<<1, 32>>>(gnpart, mr, 16, 1.f / 524288.f);

    // layer 2: 256 -> 128 (GN1+ReLU fused into B staging)
    conv_mma_kernel<256, 128, true><<<dim3(512, 1), 256, SM2>>>(
        buf1, w2, b2, buf2, mr, g1w, g1b, 8);
    gn_part_kernel<<<16 * 32, 256>>>(buf2, gnpart, 32, 32);
    gn_final_kernel<<<1, 16>>>(gnpart, mr, 32, 1.f / 524288.f);

    // layer 3: 128 -> 64 (GN2+ReLU fused into B staging)
    conv_mma_kernel<128, 64, true><<<dim3(512, 1), 256, SM3>>>(
        buf2, w3, b3, buf3, mr, g2w, g2b, 4);
    gn_part_kernel<<<16 * 32, 256>>>(buf3, gnpart, 16, 32);
    gn_final_kernel<<<1, 16>>>(gnpart, mr, 32, 1.f / 262144.f);

    // pooling (GN3+ReLU fused at read) + heads
    pool_acc_kernel<<<dim3(32, BATCH), 256>>>(buf3, masks, mr, g3w, g3b, partial, pcnt);
    heads_kernel<<<dim3(BATCH, KIDS), 64>>>(partial, pcnt, wb, bb, wc, bc, out);
}

// round 8
// speedup vs baseline: 1.1561x; 1.1561x over previous
#include <cuda_runtime.h>
#include <cstdint>
#include <math.h>

#define HH 128
#define WW 128
#define HWP 16384
#define BATCH 4
#define KIDS 20

// ---------------- scratch (device globals; no allocation) ----------------
__device__ float g_buf1[BATCH * 256 * HWP];   // 67 MB
__device__ float g_buf2[BATCH * 128 * HWP];   // 33.5 MB
__device__ float g_buf3[BATCH * 64 * HWP];    // 16.8 MB
__device__ float g_mr[64];                    // mean/rstd pairs
__device__ float g_gnpart[4096];              // GN partial sums
__device__ float g_partial[BATCH * 32 * KIDS * 64];
__device__ float g_pcnt[BATCH * 32 * KIDS];

// ---------------- tf32 helpers ----------------
__device__ __forceinline__ float f2tf32f(float x) {
    uint32_t r;
    asm("cvt.rna.tf32.f32 %0, %1;" : "=r"(r) : "f"(x));
    return __uint_as_float(r);
}
__device__ __forceinline__ void mma_tf32(float* c, uint32_t a0, uint32_t a1,
                                         uint32_t a2, uint32_t a3,
                                         uint32_t b0, uint32_t b1) {
    asm volatile("mma.sync.aligned.m16n8k8.row.col.f32.tf32.tf32.f32 "
                 "{%0,%1,%2,%3}, {%4,%5,%6,%7}, {%8,%9}, {%0,%1,%2,%3};"
                 : "+f"(c[0]), "+f"(c[1]), "+f"(c[2]), "+f"(c[3])
                 : "r"(a0), "r"(a1), "r"(a2), "r"(a3), "r"(b0), "r"(b1));
}

// smem k-position permutation within each 8-k group:
// pos(kk) = (kk & ~7) + 2*(kk & 3) + ((kk & 7) >> 2)
// so thread q's fragment {k = 8*ks+q, 8*ks+q+4} is one aligned float2 at 8*ks+2q.
__device__ __forceinline__ int kpos(int kk) {
    return (kk & ~7) + 2 * (kk & 3) + ((kk & 7) >> 2);
}

// ---------------- conv as tf32 mma.sync implicit GEMM ----------------
// K order = ci*9 + t9 ascending, 8-k mma groups ascending: identical product
// set and accumulation grouping as the round-4 passing kernel.
// Chunk = 72 k = 8 input channels x all 9 taps: per-element tap index is a
// compile-time unroll constant, so the im2col div/mod ALU chains fold away.
// GN+ReLU of the previous layer fused into B staging, applied ONLY to
// in-bounds pixels (conv padding is zero in the post-activation domain).
template<int CI, int CO, bool GN>
__global__ __launch_bounds__(256)
void conv_mma_kernel(const float* __restrict__ in, const float* __restrict__ wgt,
                     const float* __restrict__ bias, float* __restrict__ out,
                     const float* __restrict__ mr, const float* __restrict__ gw,
                     const float* __restrict__ gb, int Gin)
{
    constexpr int K = CI * 9;
    constexpr int NCHUNK = CI / 8;            // 72 k per chunk
    constexpr int M = (CO < 128) ? CO : 128;
    constexpr int MFRAG = M / 32;
    constexpr int SB = 78;                    // smem row stride (floats)

    extern __shared__ char smem[];
    float* As = reinterpret_cast<float*>(smem);       // [M][SB]
    float* Bs = As + M * SB;                          // [128][SB]
    float* scp = Bs + 128 * SB;                       // GN scale [CI]
    float* shp = scp + (GN ? CI : 0);

    const int tile = blockIdx.x;
    const int b = tile >> 7;
    const int y = tile & 127;
    const int m0 = blockIdx.y * M;
    const int tid = threadIdx.x;
    const int w = tid >> 5;
    const int lane = tid & 31;
    const int g = lane >> 2;
    const int q = lane & 3;
    const int warpM = w >> 2;
    const int warpN = w & 3;
    const int m0w = warpM * (M / 2);
    const int n0w = warpN * 32;

    if (GN) {
        const int CPG = CI / Gin;
        for (int c = tid; c < CI; c += 256) {
            int gi = c / CPG;
            float mean = mr[(b * Gin + gi) * 2 + 0];
            float rstd = mr[(b * Gin + gi) * 2 + 1];
            float s = rstd * gw[c];
            scp[c] = s;
            shp[c] = gb[c] - mean * s;
        }
    }

    const float* inB = in + (size_t)b * CI * HWP;
    const int px = tid & 127;
    const int khalf = tid >> 7;        // 0/1 -> local channels 0..3 / 4..7

    // hoisted im2col geometry (per thread, constant over all chunks)
    const int py[3]  = { (y - 1) * WW, y * WW, (y + 1) * WW };
    const int pxx[3] = { px - 1, px, px + 1 };
    const bool vy[3] = { y > 0, true, y < 127 };
    const bool vx[3] = { px > 0, true, px < 127 };

    float acc[MFRAG][4][4];
#pragma unroll
    for (int mi = 0; mi < MFRAG; mi++)
#pragma unroll
        for (int ni = 0; ni < 4; ni++)
#pragma unroll
            for (int j = 0; j < 4; j++) acc[mi][ni][j] = 0.f;

    for (int chunk = 0; chunk < NCHUNK; chunk++) {
        const int kbase = chunk * 72;
        __syncthreads();   // previous compute done before overwrite

        // ---- stage A (weights, original layout, float4 loads, cvt at stage)
#pragma unroll
        for (int it = 0; it < (M * 18 + 255) / 256; it++) {
            int idx = tid + it * 256;
            if (idx < M * 18) {
                int row = idx / 18;
                int m = idx - row * 18;
                int c4 = m * 4;
                float4 v = *reinterpret_cast<const float4*>(
                    wgt + (size_t)(m0 + row) * K + kbase + c4);
                int p0 = (c4 & ~7) | ((c4 >> 2) & 1);
                float* dst = As + row * SB + p0;
                dst[0] = f2tf32f(v.x);
                dst[2] = f2tf32f(v.y);
                dst[4] = f2tf32f(v.z);
                dst[6] = f2tf32f(v.w);
            }
        }
        // ---- stage B (im2col, compile-time taps, GN+ReLU fused IN-BOUNDS ONLY)
        {
            const int cib = chunk * 8 + khalf * 4;
            float* brow = Bs + px * SB;
#pragma unroll
            for (int jc = 0; jc < 4; jc++) {
                const float* pc = inB + (size_t)(cib + jc) * HWP;
                float s = 0.f, h = 0.f;
                if (GN) { s = scp[cib + jc]; h = shp[cib + jc]; }
                const int kb = (khalf * 4 + jc) * 9;
#pragma unroll
                for (int t = 0; t < 9; t++) {
                    const int dy = t / 3;          // compile-time 0..2
                    const int dx = t - dy * 3;     // compile-time 0..2
                    float v = 0.f;
                    if (vy[dy] && vx[dx]) {
                        v = pc[py[dy] + pxx[dx]];
                        if (GN) v = fmaxf(fmaf(v, s, h), 0.f);
                    }
                    brow[kpos(kb + t)] = f2tf32f(v);
                }
            }
        }
        __syncthreads();

        // ---- compute: 9 k-steps of m16n8k8
#pragma unroll
        for (int ks = 0; ks < 9; ks++) {
            uint32_t af[MFRAG][4];
#pragma unroll
            for (int mi = 0; mi < MFRAG; mi++) {
                int row = m0w + mi * 16 + g;
                float2 lo = *reinterpret_cast<const float2*>(As + row * SB + 8 * ks + 2 * q);
                float2 hi = *reinterpret_cast<const float2*>(As + (row + 8) * SB + 8 * ks + 2 * q);
                af[mi][0] = __float_as_uint(lo.x);
                af[mi][1] = __float_as_uint(hi.x);
                af[mi][2] = __float_as_uint(lo.y);
                af[mi][3] = __float_as_uint(hi.y);
            }
#pragma unroll
            for (int ni = 0; ni < 4; ni++) {
                int pxn = n0w + ni * 8 + g;
                float2 vb = *reinterpret_cast<const float2*>(Bs + pxn * SB + 8 * ks + 2 * q);
                uint32_t b0 = __float_as_uint(vb.x);
                uint32_t b1 = __float_as_uint(vb.y);
#pragma unroll
                for (int mi = 0; mi < MFRAG; mi++)
                    mma_tf32(acc[mi][ni], af[mi][0], af[mi][1], af[mi][2], af[mi][3], b0, b1);
            }
        }
    }

    // ---- epilogue: +bias, store NCHW as float2 pairs
#pragma unroll
    for (int mi = 0; mi < MFRAG; mi++) {
        int colo = m0 + m0w + mi * 16 + g;
        int cohi = colo + 8;
        float blo = bias[colo];
        float bhi = bias[cohi];
        float* dlo = out + (((size_t)(b * CO + colo)) * HH + y) * WW;
        float* dhi = out + (((size_t)(b * CO + cohi)) * HH + y) * WW;
#pragma unroll
        for (int ni = 0; ni < 4; ni++) {
            int x0 = n0w + ni * 8 + 2 * q;
            float2 v0 = make_float2(acc[mi][ni][0] + blo, acc[mi][ni][1] + blo);
            float2 v1 = make_float2(acc[mi][ni][2] + bhi, acc[mi][ni][3] + bhi);
            *reinterpret_cast<float2*>(dlo + x0) = v0;
            *reinterpret_cast<float2*>(dhi + x0) = v1;
        }
    }
}

// ---------------- GroupNorm statistics: partial pass ----------------
__global__ void gn_part_kernel(const float* __restrict__ x, float* __restrict__ part,
                               int Cg, int SL)
{
    const int bg = blockIdx.x / SL;
    const int sl = blockIdx.x % SL;
    const size_t n = (size_t)Cg * HWP;
    const size_t cn = n / SL;
    const float4* p = reinterpret_cast<const float4*>(x + (size_t)bg * n + (size_t)sl * cn);
    const int n4 = (int)(cn >> 2);

    float s = 0.f, ss = 0.f;
    for (int i = threadIdx.x; i < n4; i += 256) {
        float4 v = p[i];
        s  += v.x + v.y + v.z + v.w;
        ss += v.x * v.x + v.y * v.y + v.z * v.z + v.w * v.w;
    }
    __shared__ float sh_s[256], sh_ss[256];
    sh_s[threadIdx.x] = s;
    sh_ss[threadIdx.x] = ss;
    __syncthreads();
    for (int st = 128; st > 0; st >>= 1) {
        if ((int)threadIdx.x < st) {
            sh_s[threadIdx.x]  += sh_s[threadIdx.x + st];
            sh_ss[threadIdx.x] += sh_ss[threadIdx.x + st];
        }
        __syncthreads();
    }
    if (threadIdx.x == 0) {
        part[blockIdx.x * 2 + 0] = sh_s[0];
        part[blockIdx.x * 2 + 1] = sh_ss[0];
    }
}

// ---------------- GroupNorm statistics: final reduce ----------------
__global__ void gn_final_kernel(const float* __restrict__ part, float* __restrict__ mr,
                                int SL, float inv_n)
{
    const int bg = threadIdx.x;
    float s = 0.f, ss = 0.f;
    for (int i = 0; i < SL; i++) {
        s  += part[(bg * SL + i) * 2 + 0];
        ss += part[(bg * SL + i) * 2 + 1];
    }
    float mean = s * inv_n;
    float var = ss * inv_n - mean * mean;
    mr[bg * 2 + 0] = mean;
    mr[bg * 2 + 1] = rsqrtf(var + 1e-5f);
}

// ---------------- masked segment pooling (GN3+ReLU fused at read) ----------------
__global__ void pool_acc_kernel(const float* __restrict__ h, const int* __restrict__ masks,
                                const float* __restrict__ mr, const float* __restrict__ gw,
                                const float* __restrict__ gb,
                                float* __restrict__ partial, float* __restrict__ pcnt)
{
    const int b = blockIdx.y;
    const int chunk = blockIdx.x;
    const int tid = threadIdx.x;

    __shared__ float s_sums[KIDS * 65];
    __shared__ float s_cnt[KIDS];
    __shared__ float sc[64], sh[64];
    for (int i = tid; i < KIDS * 65; i += 256) s_sums[i] = 0.f;
    if (tid < KIDS) s_cnt[tid] = 0.f;
    if (tid < 64) {
        int g = tid >> 4;
        float mean = mr[(b * 4 + g) * 2 + 0];
        float rstd = mr[(b * 4 + g) * 2 + 1];
        float s = rstd * gw[tid];
        sc[tid] = s;
        sh[tid] = gb[tid] - mean * s;
    }
    __syncthreads();

    const float* hb = h + (size_t)b * 64 * HWP;
    const int* mb = masks + b * HWP;

    const int p0 = chunk * 512;
    for (int p = p0 + tid; p < p0 + 512; p += 256) {
        int k = mb[p] - 1;
        if (k >= 0) {
            atomicAdd(&s_cnt[k], 1.f);
#pragma unroll
            for (int c = 0; c < 64; c++) {
                float v = fmaxf(fmaf(hb[c * HWP + p], sc[c], sh[c]), 0.f);
                atomicAdd(&s_sums[k * 65 + c], v);
            }
        }
    }
    __syncthreads();

    float* pb = partial + (size_t)(b * 32 + chunk) * (KIDS * 64);
    for (int i = tid; i < KIDS * 64; i += 256) {
        int k = i >> 6, c = i & 63;
        pb[i] = s_sums[k * 65 + c];
    }
    if (tid < KIDS) pcnt[(b * 32 + chunk) * KIDS + tid] = s_cnt[tid];
}

// ---------------- reduce partials + dense heads ----------------
__global__ void heads_kernel(const float* __restrict__ partial, const float* __restrict__ pcnt,
                             const float* __restrict__ wb, const float* __restrict__ bb,
                             const float* __restrict__ wc, const float* __restrict__ bc,
                             float* __restrict__ out)
{
    const int b = blockIdx.x;
    const int k = blockIdx.y;
    const int c = threadIdx.x;

    float s = 0.f;
    for (int ch = 0; ch < 32; ch++)
        s += partial[(size_t)(b * 32 + ch) * (KIDS * 64) + k * 64 + c];
    float cnt = 0.f;
    for (int ch = 0; ch < 32; ch++)
        cnt += pcnt[(b * 32 + ch) * KIDS + k];
    float pooled = s / (cnt + 1e-6f);

    __shared__ float red[64];
#pragma unroll
    for (int o = 0; o < 7; o++) {
        red[c] = pooled * wb[o * 64 + c];
        __syncthreads();
        for (int st = 32; st > 0; st >>= 1) {
            if (c < st) red[c] += red[c + st];
            __syncthreads();
        }
        if (c == 0) out[(b * KIDS + k) * 7 + o] = red[0] + bb[o];
        __syncthreads();
    }
    red[c] = pooled * wc[c];
    __syncthreads();
    for (int st = 32; st > 0; st >>= 1) {
        if (c < st) red[c] += red[c + st];
        __syncthreads();
    }
    if (c == 0) {
        float z = red[0] + bc[0];
        out[BATCH * KIDS * 7 + b * KIDS + k] = 1.f / (1.f + expf(-z));
    }
}

// ---------------- launch ----------------
extern "C" void kernel_launch(void* const* d_in, const int* in_sizes, int n_in,
                              void* d_out, int out_size)
{
    const float* x    = (const float*)d_in[0];
    const int*   masks= (const int*)  d_in[1];
    const float* w1   = (const float*)d_in[2];
    const float* b1   = (const float*)d_in[3];
    const float* g1w  = (const float*)d_in[4];
    const float* g1b  = (const float*)d_in[5];
    const float* w2   = (const float*)d_in[6];
    const float* b2   = (const float*)d_in[7];
    const float* g2w  = (const float*)d_in[8];
    const float* g2b  = (const float*)d_in[9];
    const float* w3   = (const float*)d_in[10];
    const float* b3   = (const float*)d_in[11];
    const float* g3w  = (const float*)d_in[12];
    const float* g3b  = (const float*)d_in[13];
    const float* wb   = (const float*)d_in[14];
    const float* bb   = (const float*)d_in[15];
    const float* wc   = (const float*)d_in[16];
    const float* bc   = (const float*)d_in[17];
    float* out = (float*)d_out;

    float *buf1, *buf2, *buf3, *mr, *gnpart, *partial, *pcnt;
    cudaGetSymbolAddress((void**)&buf1, g_buf1);
    cudaGetSymbolAddress((void**)&buf2, g_buf2);
    cudaGetSymbolAddress((void**)&buf3, g_buf3);
    cudaGetSymbolAddress((void**)&mr, g_mr);
    cudaGetSymbolAddress((void**)&gnpart, g_gnpart);
    cudaGetSymbolAddress((void**)&partial, g_partial);
    cudaGetSymbolAddress((void**)&pcnt, g_pcnt);

    // dynamic smem: (M + 128) * 78 * 4 + GN arrays
    const int SM1 = (128 + 128) * 78 * 4;                 // 79872
    const int SM2 = (128 + 128) * 78 * 4 + 2 * 256 * 4;   // 81920
    const int SM3 = (64 + 128) * 78 * 4 + 2 * 128 * 4;    // 60928
    cudaFuncSetAttribute(conv_mma_kernel<512, 256, false>,
                         cudaFuncAttributeMaxDynamicSharedMemorySize, SM1);
    cudaFuncSetAttribute(conv_mma_kernel<256, 128, true>,
                         cudaFuncAttributeMaxDynamicSharedMemorySize, SM2);
    cudaFuncSetAttribute(conv_mma_kernel<128, 64, true>,
                         cudaFuncAttributeMaxDynamicSharedMemorySize, SM3);

    // layer 1: 512 -> 256
    conv_mma_kernel<512, 256, false><<<dim3(512, 2), 256, SM1>>>(
        x, w1, b1, buf1, nullptr, nullptr, nullptr, 0);
    gn_part_kernel<<<32 * 16, 256>>>(buf1, gnpart, 32, 16);
    gn_final_kernel<<<1, 32>>>(gnpart, mr, 16, 1.f / 524288.f);

    // layer 2: 256 -> 128 (GN1+ReLU fused into B staging)
    conv_mma_kernel<256, 128, true><<<dim3(512, 1), 256, SM2>>>(
        buf1, w2, b2, buf2, mr, g1w, g1b, 8);
    gn_part_kernel<<<16 * 32, 256>>>(buf2, gnpart, 32, 32);
    gn_final_kernel<<<1, 16>>>(gnpart, mr, 32, 1.f / 524288.f);

    // layer 3: 128 -> 64 (GN2+ReLU fused into B staging)
    conv_mma_kernel<128, 64, true><<<dim3(512, 1), 256, SM3>>>(
        buf2, w3, b3, buf3, mr, g2w, g2b, 4);
    gn_part_kernel<<<16 * 32, 256>>>(buf3, gnpart, 16, 32);
    gn_final_kernel<<<1, 16>>>(gnpart, mr, 32, 1.f / 262144.f);

    // pooling (GN3+ReLU fused at read) + heads
    pool_acc_kernel<<<dim3(32, BATCH), 256>>>(buf3, masks, mr, g3w, g3b, partial, pcnt);
    heads_kernel<<<dim3(BATCH, KIDS), 64>>>(partial, pcnt, wb, bb, wc, bc, out);
}

// round 9
// speedup vs baseline: 1.2539x; 1.0846x over previous
#include <cuda_runtime.h>
#include <cstdint>
#include <math.h>

#define HH 128
#define WW 128
#define HWP 16384
#define BATCH 4
#define KIDS 20

// ---------------- scratch (device globals; no allocation) ----------------
__device__ float g_buf1[BATCH * 256 * HWP];   // 67 MB
__device__ float g_buf2[BATCH * 128 * HWP];   // 33.5 MB
__device__ float g_buf3[BATCH * 64 * HWP];    // 16.8 MB
__device__ float g_mr[64];                    // mean/rstd pairs
__device__ float g_gnpart[4096];              // GN partial sums
__device__ float g_partial[BATCH * 32 * KIDS * 64];
__device__ float g_pcnt[BATCH * 32 * KIDS];

// ---------------- tf32 helpers ----------------
__device__ __forceinline__ float f2tf32f(float x) {
    uint32_t r;
    asm("cvt.rna.tf32.f32 %0, %1;" : "=r"(r) : "f"(x));
    return __uint_as_float(r);
}
__device__ __forceinline__ void mma_tf32(float* c, uint32_t a0, uint32_t a1,
                                         uint32_t a2, uint32_t a3,
                                         uint32_t b0, uint32_t b1) {
    asm volatile("mma.sync.aligned.m16n8k8.row.col.f32.tf32.tf32.f32 "
                 "{%0,%1,%2,%3}, {%4,%5,%6,%7}, {%8,%9}, {%0,%1,%2,%3};"
                 : "+f"(c[0]), "+f"(c[1]), "+f"(c[2]), "+f"(c[3])
                 : "r"(a0), "r"(a1), "r"(a2), "r"(a3), "r"(b0), "r"(b1));
}

// smem k-position permutation within each 8-k group:
// pos(kk) = (kk & ~7) + 2*(kk & 3) + ((kk & 7) >> 2)
// so thread q's fragment {k = 8*ks+q, 8*ks+q+4} is one aligned float2 at 8*ks+2q.
__device__ __forceinline__ int kpos(int kk) {
    return (kk & ~7) + 2 * (kk & 3) + ((kk & 7) >> 2);
}

// ---------------- conv as tf32 mma.sync implicit GEMM ----------------
// Identical numerics to round 8 (passing, rel_err 1.7915e-4). Single change:
// __launch_bounds__(256, 2) caps registers at 128 so 2 CTAs co-reside per SM,
// restoring cross-CTA latency hiding for the staging + sync bubbles.
template<int CI, int CO, bool GN>
__global__ __launch_bounds__(256, 2)
void conv_mma_kernel(const float* __restrict__ in, const float* __restrict__ wgt,
                     const float* __restrict__ bias, float* __restrict__ out,
                     const float* __restrict__ mr, const float* __restrict__ gw,
                     const float* __restrict__ gb, int Gin)
{
    constexpr int K = CI * 9;
    constexpr int NCHUNK = CI / 8;            // 72 k per chunk
    constexpr int M = (CO < 128) ? CO : 128;
    constexpr int MFRAG = M / 32;
    constexpr int SB = 78;                    // smem row stride (floats)

    extern __shared__ char smem[];
    float* As = reinterpret_cast<float*>(smem);       // [M][SB]
    float* Bs = As + M * SB;                          // [128][SB]
    float* scp = Bs + 128 * SB;                       // GN scale [CI]
    float* shp = scp + (GN ? CI : 0);

    const int tile = blockIdx.x;
    const int b = tile >> 7;
    const int y = tile & 127;
    const int m0 = blockIdx.y * M;
    const int tid = threadIdx.x;
    const int w = tid >> 5;
    const int lane = tid & 31;
    const int g = lane >> 2;
    const int q = lane & 3;
    const int warpM = w >> 2;
    const int warpN = w & 3;
    const int m0w = warpM * (M / 2);
    const int n0w = warpN * 32;

    if (GN) {
        const int CPG = CI / Gin;
        for (int c = tid; c < CI; c += 256) {
            int gi = c / CPG;
            float mean = mr[(b * Gin + gi) * 2 + 0];
            float rstd = mr[(b * Gin + gi) * 2 + 1];
            float s = rstd * gw[c];
            scp[c] = s;
            shp[c] = gb[c] - mean * s;
        }
    }

    const float* inB = in + (size_t)b * CI * HWP;
    const int px = tid & 127;
    const int khalf = tid >> 7;        // 0/1 -> local channels 0..3 / 4..7

    // hoisted im2col geometry (per thread, constant over all chunks)
    const int py[3]  = { (y - 1) * WW, y * WW, (y + 1) * WW };
    const int pxx[3] = { px - 1, px, px + 1 };
    const bool vy[3] = { y > 0, true, y < 127 };
    const bool vx[3] = { px > 0, true, px < 127 };

    float acc[MFRAG][4][4];
#pragma unroll
    for (int mi = 0; mi < MFRAG; mi++)
#pragma unroll
        for (int ni = 0; ni < 4; ni++)
#pragma unroll
            for (int j = 0; j < 4; j++) acc[mi][ni][j] = 0.f;

    for (int chunk = 0; chunk < NCHUNK; chunk++) {
        const int kbase = chunk * 72;
        __syncthreads();   // previous compute done before overwrite

        // ---- stage A (weights, original layout, float4 loads, cvt at stage)
#pragma unroll
        for (int it = 0; it < (M * 18 + 255) / 256; it++) {
            int idx = tid + it * 256;
            if (idx < M * 18) {
                int row = idx / 18;
                int m = idx - row * 18;
                int c4 = m * 4;
                float4 v = *reinterpret_cast<const float4*>(
                    wgt + (size_t)(m0 + row) * K + kbase + c4);
                int p0 = (c4 & ~7) | ((c4 >> 2) & 1);
                float* dst = As + row * SB + p0;
                dst[0] = f2tf32f(v.x);
                dst[2] = f2tf32f(v.y);
                dst[4] = f2tf32f(v.z);
                dst[6] = f2tf32f(v.w);
            }
        }
        // ---- stage B (im2col, compile-time taps, GN+ReLU fused IN-BOUNDS ONLY)
        {
            const int cib = chunk * 8 + khalf * 4;
            float* brow = Bs + px * SB;
#pragma unroll
            for (int jc = 0; jc < 4; jc++) {
                const float* pc = inB + (size_t)(cib + jc) * HWP;
                float s = 0.f, h = 0.f;
                if (GN) { s = scp[cib + jc]; h = shp[cib + jc]; }
                const int kb = (khalf * 4 + jc) * 9;
#pragma unroll
                for (int t = 0; t < 9; t++) {
                    const int dy = t / 3;          // compile-time 0..2
                    const int dx = t - dy * 3;     // compile-time 0..2
                    float v = 0.f;
                    if (vy[dy] && vx[dx]) {
                        v = pc[py[dy] + pxx[dx]];
                        if (GN) v = fmaxf(fmaf(v, s, h), 0.f);
                    }
                    brow[kpos(kb + t)] = f2tf32f(v);
                }
            }
        }
        __syncthreads();

        // ---- compute: 9 k-steps of m16n8k8
#pragma unroll
        for (int ks = 0; ks < 9; ks++) {
            uint32_t af[MFRAG][4];
#pragma unroll
            for (int mi = 0; mi < MFRAG; mi++) {
                int row = m0w + mi * 16 + g;
                float2 lo = *reinterpret_cast<const float2*>(As + row * SB + 8 * ks + 2 * q);
                float2 hi = *reinterpret_cast<const float2*>(As + (row + 8) * SB + 8 * ks + 2 * q);
                af[mi][0] = __float_as_uint(lo.x);
                af[mi][1] = __float_as_uint(hi.x);
                af[mi][2] = __float_as_uint(lo.y);
                af[mi][3] = __float_as_uint(hi.y);
            }
#pragma unroll
            for (int ni = 0; ni < 4; ni++) {
                int pxn = n0w + ni * 8 + g;
                float2 vb = *reinterpret_cast<const float2*>(Bs + pxn * SB + 8 * ks + 2 * q);
                uint32_t b0 = __float_as_uint(vb.x);
                uint32_t b1 = __float_as_uint(vb.y);
#pragma unroll
                for (int mi = 0; mi < MFRAG; mi++)
                    mma_tf32(acc[mi][ni], af[mi][0], af[mi][1], af[mi][2], af[mi][3], b0, b1);
            }
        }
    }

    // ---- epilogue: +bias, store NCHW as float2 pairs
#pragma unroll
    for (int mi = 0; mi < MFRAG; mi++) {
        int colo = m0 + m0w + mi * 16 + g;
        int cohi = colo + 8;
        float blo = bias[colo];
        float bhi = bias[cohi];
        float* dlo = out + (((size_t)(b * CO + colo)) * HH + y) * WW;
        float* dhi = out + (((size_t)(b * CO + cohi)) * HH + y) * WW;
#pragma unroll
        for (int ni = 0; ni < 4; ni++) {
            int x0 = n0w + ni * 8 + 2 * q;
            float2 v0 = make_float2(acc[mi][ni][0] + blo, acc[mi][ni][1] + blo);
            float2 v1 = make_float2(acc[mi][ni][2] + bhi, acc[mi][ni][3] + bhi);
            *reinterpret_cast<float2*>(dlo + x0) = v0;
            *reinterpret_cast<float2*>(dhi + x0) = v1;
        }
    }
}

// ---------------- GroupNorm statistics: partial pass ----------------
__global__ void gn_part_kernel(const float* __restrict__ x, float* __restrict__ part,
                               int Cg, int SL)
{
    const int bg = blockIdx.x / SL;
    const int sl = blockIdx.x % SL;
    const size_t n = (size_t)Cg * HWP;
    const size_t cn = n / SL;
    const float4* p = reinterpret_cast<const float4*>(x + (size_t)bg * n + (size_t)sl * cn);
    const int n4 = (int)(cn >> 2);

    float s = 0.f, ss = 0.f;
    for (int i = threadIdx.x; i < n4; i += 256) {
        float4 v = p[i];
        s  += v.x + v.y + v.z + v.w;
        ss += v.x * v.x + v.y * v.y + v.z * v.z + v.w * v.w;
    }
    __shared__ float sh_s[256], sh_ss[256];
    sh_s[threadIdx.x] = s;
    sh_ss[threadIdx.x] = ss;
    __syncthreads();
    for (int st = 128; st > 0; st >>= 1) {
        if ((int)threadIdx.x < st) {
            sh_s[threadIdx.x]  += sh_s[threadIdx.x + st];
            sh_ss[threadIdx.x] += sh_ss[threadIdx.x + st];
        }
        __syncthreads();
    }
    if (threadIdx.x == 0) {
        part[blockIdx.x * 2 + 0] = sh_s[0];
        part[blockIdx.x * 2 + 1] = sh_ss[0];
    }
}

// ---------------- GroupNorm statistics: final reduce ----------------
__global__ void gn_final_kernel(const float* __restrict__ part, float* __restrict__ mr,
                                int SL, float inv_n)
{
    const int bg = threadIdx.x;
    float s = 0.f, ss = 0.f;
    for (int i = 0; i < SL; i++) {
        s  += part[(bg * SL + i) * 2 + 0];
        ss += part[(bg * SL + i) * 2 + 1];
    }
    float mean = s * inv_n;
    float var = ss * inv_n - mean * mean;
    mr[bg * 2 + 0] = mean;
    mr[bg * 2 + 1] = rsqrtf(var + 1e-5f);
}

// ---------------- masked segment pooling (GN3+ReLU fused at read) ----------------
__global__ void pool_acc_kernel(const float* __restrict__ h, const int* __restrict__ masks,
                                const float* __restrict__ mr, const float* __restrict__ gw,
                                const float* __restrict__ gb,
                                float* __restrict__ partial, float* __restrict__ pcnt)
{
    const int b = blockIdx.y;
    const int chunk = blockIdx.x;
    const int tid = threadIdx.x;

    __shared__ float s_sums[KIDS * 65];
    __shared__ float s_cnt[KIDS];
    __shared__ float sc[64], sh[64];
    for (int i = tid; i < KIDS * 65; i += 256) s_sums[i] = 0.f;
    if (tid < KIDS) s_cnt[tid] = 0.f;
    if (tid < 64) {
        int g = tid >> 4;
        float mean = mr[(b * 4 + g) * 2 + 0];
        float rstd = mr[(b * 4 + g) * 2 + 1];
        float s = rstd * gw[tid];
        sc[tid] = s;
        sh[tid] = gb[tid] - mean * s;
    }
    __syncthreads();

    const float* hb = h + (size_t)b * 64 * HWP;
    const int* mb = masks + b * HWP;

    const int p0 = chunk * 512;
    for (int p = p0 + tid; p < p0 + 512; p += 256) {
        int k = mb[p] - 1;
        if (k >= 0) {
            atomicAdd(&s_cnt[k], 1.f);
#pragma unroll
            for (int c = 0; c < 64; c++) {
                float v = fmaxf(fmaf(hb[c * HWP + p], sc[c], sh[c]), 0.f);
                atomicAdd(&s_sums[k * 65 + c], v);
            }
        }
    }
    __syncthreads();

    float* pb = partial + (size_t)(b * 32 + chunk) * (KIDS * 64);
    for (int i = tid; i < KIDS * 64; i += 256) {
        int k = i >> 6, c = i & 63;
        pb[i] = s_sums[k * 65 + c];
    }
    if (tid < KIDS) pcnt[(b * 32 + chunk) * KIDS + tid] = s_cnt[tid];
}

// ---------------- reduce partials + dense heads ----------------
__global__ void heads_kernel(const float* __restrict__ partial, const float* __restrict__ pcnt,
                             const float* __restrict__ wb, const float* __restrict__ bb,
                             const float* __restrict__ wc, const float* __restrict__ bc,
                             float* __restrict__ out)
{
    const int b = blockIdx.x;
    const int k = blockIdx.y;
    const int c = threadIdx.x;

    float s = 0.f;
    for (int ch = 0; ch < 32; ch++)
        s += partial[(size_t)(b * 32 + ch) * (KIDS * 64) + k * 64 + c];
    float cnt = 0.f;
    for (int ch = 0; ch < 32; ch++)
        cnt += pcnt[(b * 32 + ch) * KIDS + k];
    float pooled = s / (cnt + 1e-6f);

    __shared__ float red[64];
#pragma unroll
    for (int o = 0; o < 7; o++) {
        red[c] = pooled * wb[o * 64 + c];
        __syncthreads();
        for (int st = 32; st > 0; st >>= 1) {
            if (c < st) red[c] += red[c + st];
            __syncthreads();
        }
        if (c == 0) out[(b * KIDS + k) * 7 + o] = red[0] + bb[o];
        __syncthreads();
    }
    red[c] = pooled * wc[c];
    __syncthreads();
    for (int st = 32; st > 0; st >>= 1) {
        if (c < st) red[c] += red[c + st];
        __syncthreads();
    }
    if (c == 0) {
        float z = red[0] + bc[0];
        out[BATCH * KIDS * 7 + b * KIDS + k] = 1.f / (1.f + expf(-z));
    }
}

// ---------------- launch ----------------
extern "C" void kernel_launch(void* const* d_in, const int* in_sizes, int n_in,
                              void* d_out, int out_size)
{
    const float* x    = (const float*)d_in[0];
    const int*   masks= (const int*)  d_in[1];
    const float* w1   = (const float*)d_in[2];
    const float* b1   = (const float*)d_in[3];
    const float* g1w  = (const float*)d_in[4];
    const float* g1b  = (const float*)d_in[5];
    const float* w2   = (const float*)d_in[6];
    const float* b2   = (const float*)d_in[7];
    const float* g2w  = (const float*)d_in[8];
    const float* g2b  = (const float*)d_in[9];
    const float* w3   = (const float*)d_in[10];
    const float* b3   = (const float*)d_in[11];
    const float* g3w  = (const float*)d_in[12];
    const float* g3b  = (const float*)d_in[13];
    const float* wb   = (const float*)d_in[14];
    const float* bb   = (const float*)d_in[15];
    const float* wc   = (const float*)d_in[16];
    const float* bc   = (const float*)d_in[17];
    float* out = (float*)d_out;

    float *buf1, *buf2, *buf3, *mr, *gnpart, *partial, *pcnt;
    cudaGetSymbolAddress((void**)&buf1, g_buf1);
    cudaGetSymbolAddress((void**)&buf2, g_buf2);
    cudaGetSymbolAddress((void**)&buf3, g_buf3);
    cudaGetSymbolAddress((void**)&mr, g_mr);
    cudaGetSymbolAddress((void**)&gnpart, g_gnpart);
    cudaGetSymbolAddress((void**)&partial, g_partial);
    cudaGetSymbolAddress((void**)&pcnt, g_pcnt);

    // dynamic smem: (M + 128) * 78 * 4 + GN arrays
    const int SM1 = (128 + 128) * 78 * 4;                 // 79872
    const int SM2 = (128 + 128) * 78 * 4 + 2 * 256 * 4;   // 81920
    const int SM3 = (64 + 128) * 78 * 4 + 2 * 128 * 4;    // 60928
    cudaFuncSetAttribute(conv_mma_kernel<512, 256, false>,
                         cudaFuncAttributeMaxDynamicSharedMemorySize, SM1);
    cudaFuncSetAttribute(conv_mma_kernel<256, 128, true>,
                         cudaFuncAttributeMaxDynamicSharedMemorySize, SM2);
    cudaFuncSetAttribute(conv_mma_kernel<128, 64, true>,
                         cudaFuncAttributeMaxDynamicSharedMemorySize, SM3);

    // layer 1: 512 -> 256
    conv_mma_kernel<512, 256, false><<<dim3(512, 2), 256, SM1>>>(
        x, w1, b1, buf1, nullptr, nullptr, nullptr, 0);
    gn_part_kernel<<<32 * 16, 256>>>(buf1, gnpart, 32, 16);
    gn_final_kernel<<<1, 32>>>(gnpart, mr, 16, 1.f / 524288.f);

    // layer 2: 256 -> 128 (GN1+ReLU fused into B staging)
    conv_mma_kernel<256, 128, true><<<dim3(512, 1), 256, SM2>>>(
        buf1, w2, b2, buf2, mr, g1w, g1b, 8);
    gn_part_kernel<<<16 * 32, 256>>>(buf2, gnpart, 32, 32);
    gn_final_kernel<<<1, 16>>>(gnpart, mr, 32, 1.f / 524288.f);

    // layer 3: 128 -> 64 (GN2+ReLU fused into B staging)
    conv_mma_kernel<128, 64, true><<<dim3(512, 1), 256, SM3>>>(
        buf2, w3, b3, buf3, mr, g2w, g2b, 4);
    gn_part_kernel<<<16 * 32, 256>>>(buf3, gnpart, 16, 32);
    gn_final_kernel<<<1, 16>>>(gnpart, mr, 32, 1.f / 262144.f);

    // pooling (GN3+ReLU fused at read) + heads
    pool_acc_kernel<<<dim3(32, BATCH), 256>>>(buf3, masks, mr, g3w, g3b, partial, pcnt);
    heads_kernel<<<dim3(BATCH, KIDS), 64>>>(partial, pcnt, wb, bb, wc, bc, out);
}

// round 10
// speedup vs baseline: 1.4780x; 1.1787x over previous
#include <cuda_runtime.h>
#include <cstdint>
#include <math.h>

#define HH 128
#define WW 128
#define HWP 16384
#define BATCH 4
#define KIDS 20

// ---------------- scratch (device globals; no allocation) ----------------
__device__ float g_buf1[BATCH * 256 * HWP];   // 67 MB
__device__ float g_buf2[BATCH * 128 * HWP];   // 33.5 MB
__device__ float g_buf3[BATCH * 64 * HWP];    // 16.8 MB
__device__ float g_mr[64];                    // mean/rstd pairs
__device__ float g_gnpart[4096];              // GN partial sums
__device__ float g_partial[BATCH * 32 * KIDS * 64];
__device__ float g_pcnt[BATCH * 32 * KIDS];

// ---------------- tf32 mma ----------------
// NOTE: operands are fed as raw fp32 — tf32 HMMA reads the top 19 bits of the
// register (sign/8-bit exp/10-bit mantissa), i.e. truncation rounding. This
// removes the cvt.rna.tf32 instruction from every staged element (the cvt
// stream was ~2x the entire compute instruction stream per chunk).
__device__ __forceinline__ void mma_tf32(float* c, uint32_t a0, uint32_t a1,
                                         uint32_t a2, uint32_t a3,
                                         uint32_t b0, uint32_t b1) {
    asm volatile("mma.sync.aligned.m16n8k8.row.col.f32.tf32.tf32.f32 "
                 "{%0,%1,%2,%3}, {%4,%5,%6,%7}, {%8,%9}, {%0,%1,%2,%3};"
                 : "+f"(c[0]), "+f"(c[1]), "+f"(c[2]), "+f"(c[3])
                 : "r"(a0), "r"(a1), "r"(a2), "r"(a3), "r"(b0), "r"(b1));
}

// smem k-position permutation within each 8-k group:
// pos(kk) = (kk & ~7) + 2*(kk & 3) + ((kk & 7) >> 2)
// so thread q's fragment {k = 8*ks+q, 8*ks+q+4} is one aligned float2 at 8*ks+2q.
__device__ __forceinline__ int kpos(int kk) {
    return (kk & ~7) + 2 * (kk & 3) + ((kk & 7) >> 2);
}

// ---------------- conv as tf32 mma.sync implicit GEMM ----------------
// Identical structure to round 9 (passing). Single change: no explicit
// tf32 conversion during staging (HW truncation, see mma_tf32 note).
template<int CI, int CO, bool GN>
__global__ __launch_bounds__(256, 2)
void conv_mma_kernel(const float* __restrict__ in, const float* __restrict__ wgt,
                     const float* __restrict__ bias, float* __restrict__ out,
                     const float* __restrict__ mr, const float* __restrict__ gw,
                     const float* __restrict__ gb, int Gin)
{
    constexpr int K = CI * 9;
    constexpr int NCHUNK = CI / 8;            // 72 k per chunk
    constexpr int M = (CO < 128) ? CO : 128;
    constexpr int MFRAG = M / 32;
    constexpr int SB = 78;                    // smem row stride (floats)

    extern __shared__ char smem[];
    float* As = reinterpret_cast<float*>(smem);       // [M][SB]
    float* Bs = As + M * SB;                          // [128][SB]
    float* scp = Bs + 128 * SB;                       // GN scale [CI]
    float* shp = scp + (GN ? CI : 0);

    const int tile = blockIdx.x;
    const int b = tile >> 7;
    const int y = tile & 127;
    const int m0 = blockIdx.y * M;
    const int tid = threadIdx.x;
    const int w = tid >> 5;
    const int lane = tid & 31;
    const int g = lane >> 2;
    const int q = lane & 3;
    const int warpM = w >> 2;
    const int warpN = w & 3;
    const int m0w = warpM * (M / 2);
    const int n0w = warpN * 32;

    if (GN) {
        const int CPG = CI / Gin;
        for (int c = tid; c < CI; c += 256) {
            int gi = c / CPG;
            float mean = mr[(b * Gin + gi) * 2 + 0];
            float rstd = mr[(b * Gin + gi) * 2 + 1];
            float s = rstd * gw[c];
            scp[c] = s;
            shp[c] = gb[c] - mean * s;
        }
    }

    const float* inB = in + (size_t)b * CI * HWP;
    const int px = tid & 127;
    const int khalf = tid >> 7;        // 0/1 -> local channels 0..3 / 4..7

    // hoisted im2col geometry (per thread, constant over all chunks)
    const int py[3]  = { (y - 1) * WW, y * WW, (y + 1) * WW };
    const int pxx[3] = { px - 1, px, px + 1 };
    const bool vy[3] = { y > 0, true, y < 127 };
    const bool vx[3] = { px > 0, true, px < 127 };

    float acc[MFRAG][4][4];
#pragma unroll
    for (int mi = 0; mi < MFRAG; mi++)
#pragma unroll
        for (int ni = 0; ni < 4; ni++)
#pragma unroll
            for (int j = 0; j < 4; j++) acc[mi][ni][j] = 0.f;

    for (int chunk = 0; chunk < NCHUNK; chunk++) {
        const int kbase = chunk * 72;
        __syncthreads();   // previous compute done before overwrite

        // ---- stage A (weights, original layout, float4 loads, no cvt)
#pragma unroll
        for (int it = 0; it < (M * 18 + 255) / 256; it++) {
            int idx = tid + it * 256;
            if (idx < M * 18) {
                int row = idx / 18;
                int m = idx - row * 18;
                int c4 = m * 4;
                float4 v = *reinterpret_cast<const float4*>(
                    wgt + (size_t)(m0 + row) * K + kbase + c4);
                int p0 = (c4 & ~7) | ((c4 >> 2) & 1);
                float* dst = As + row * SB + p0;
                dst[0] = v.x;
                dst[2] = v.y;
                dst[4] = v.z;
                dst[6] = v.w;
            }
        }
        // ---- stage B (im2col, compile-time taps, GN+ReLU fused IN-BOUNDS ONLY)
        {
            const int cib = chunk * 8 + khalf * 4;
            float* brow = Bs + px * SB;
#pragma unroll
            for (int jc = 0; jc < 4; jc++) {
                const float* pc = inB + (size_t)(cib + jc) * HWP;
                float s = 0.f, h = 0.f;
                if (GN) { s = scp[cib + jc]; h = shp[cib + jc]; }
                const int kb = (khalf * 4 + jc) * 9;
#pragma unroll
                for (int t = 0; t < 9; t++) {
                    const int dy = t / 3;          // compile-time 0..2
                    const int dx = t - dy * 3;     // compile-time 0..2
                    float v = 0.f;
                    if (vy[dy] && vx[dx]) {
                        v = pc[py[dy] + pxx[dx]];
                        if (GN) v = fmaxf(fmaf(v, s, h), 0.f);
                    }
                    brow[kpos(kb + t)] = v;
                }
            }
        }
        __syncthreads();

        // ---- compute: 9 k-steps of m16n8k8
#pragma unroll
        for (int ks = 0; ks < 9; ks++) {
            uint32_t af[MFRAG][4];
#pragma unroll
            for (int mi = 0; mi < MFRAG; mi++) {
                int row = m0w + mi * 16 + g;
                float2 lo = *reinterpret_cast<const float2*>(As + row * SB + 8 * ks + 2 * q);
                float2 hi = *reinterpret_cast<const float2*>(As + (row + 8) * SB + 8 * ks + 2 * q);
                af[mi][0] = __float_as_uint(lo.x);
                af[mi][1] = __float_as_uint(hi.x);
                af[mi][2] = __float_as_uint(lo.y);
                af[mi][3] = __float_as_uint(hi.y);
            }
#pragma unroll
            for (int ni = 0; ni < 4; ni++) {
                int pxn = n0w + ni * 8 + g;
                float2 vb = *reinterpret_cast<const float2*>(Bs + pxn * SB + 8 * ks + 2 * q);
                uint32_t b0 = __float_as_uint(vb.x);
                uint32_t b1 = __float_as_uint(vb.y);
#pragma unroll
                for (int mi = 0; mi < MFRAG; mi++)
                    mma_tf32(acc[mi][ni], af[mi][0], af[mi][1], af[mi][2], af[mi][3], b0, b1);
            }
        }
    }

    // ---- epilogue: +bias, store NCHW as float2 pairs
#pragma unroll
    for (int mi = 0; mi < MFRAG; mi++) {
        int colo = m0 + m0w + mi * 16 + g;
        int cohi = colo + 8;
        float blo = bias[colo];
        float bhi = bias[cohi];
        float* dlo = out + (((size_t)(b * CO + colo)) * HH + y) * WW;
        float* dhi = out + (((size_t)(b * CO + cohi)) * HH + y) * WW;
#pragma unroll
        for (int ni = 0; ni < 4; ni++) {
            int x0 = n0w + ni * 8 + 2 * q;
            float2 v0 = make_float2(acc[mi][ni][0] + blo, acc[mi][ni][1] + blo);
            float2 v1 = make_float2(acc[mi][ni][2] + bhi, acc[mi][ni][3] + bhi);
            *reinterpret_cast<float2*>(dlo + x0) = v0;
            *reinterpret_cast<float2*>(dhi + x0) = v1;
        }
    }
}

// ---------------- GroupNorm statistics: partial pass ----------------
__global__ void gn_part_kernel(const float* __restrict__ x, float* __restrict__ part,
                               int Cg, int SL)
{
    const int bg = blockIdx.x / SL;
    const int sl = blockIdx.x % SL;
    const size_t n = (size_t)Cg * HWP;
    const size_t cn = n / SL;
    const float4* p = reinterpret_cast<const float4*>(x + (size_t)bg * n + (size_t)sl * cn);
    const int n4 = (int)(cn >> 2);

    float s = 0.f, ss = 0.f;
    for (int i = threadIdx.x; i < n4; i += 256) {
        float4 v = p[i];
        s  += v.x + v.y + v.z + v.w;
        ss += v.x * v.x + v.y * v.y + v.z * v.z + v.w * v.w;
    }
    __shared__ float sh_s[256], sh_ss[256];
    sh_s[threadIdx.x] = s;
    sh_ss[threadIdx.x] = ss;
    __syncthreads();
    for (int st = 128; st > 0; st >>= 1) {
        if ((int)threadIdx.x < st) {
            sh_s[threadIdx.x]  += sh_s[threadIdx.x + st];
            sh_ss[threadIdx.x] += sh_ss[threadIdx.x + st];
        }
        __syncthreads();
    }
    if (threadIdx.x == 0) {
        part[blockIdx.x * 2 + 0] = sh_s[0];
        part[blockIdx.x * 2 + 1] = sh_ss[0];
    }
}

// ---------------- GroupNorm statistics: final reduce ----------------
__global__ void gn_final_kernel(const float* __restrict__ part, float* __restrict__ mr,
                                int SL, float inv_n)
{
    const int bg = threadIdx.x;
    float s = 0.f, ss = 0.f;
    for (int i = 0; i < SL; i++) {
        s  += part[(bg * SL + i) * 2 + 0];
        ss += part[(bg * SL + i) * 2 + 1];
    }
    float mean = s * inv_n;
    float var = ss * inv_n - mean * mean;
    mr[bg * 2 + 0] = mean;
    mr[bg * 2 + 1] = rsqrtf(var + 1e-5f);
}

// ---------------- masked segment pooling (GN3+ReLU fused at read) ----------------
__global__ void pool_acc_kernel(const float* __restrict__ h, const int* __restrict__ masks,
                                const float* __restrict__ mr, const float* __restrict__ gw,
                                const float* __restrict__ gb,
                                float* __restrict__ partial, float* __restrict__ pcnt)
{
    const int b = blockIdx.y;
    const int chunk = blockIdx.x;
    const int tid = threadIdx.x;

    __shared__ float s_sums[KIDS * 65];
    __shared__ float s_cnt[KIDS];
    __shared__ float sc[64], sh[64];
    for (int i = tid; i < KIDS * 65; i += 256) s_sums[i] = 0.f;
    if (tid < KIDS) s_cnt[tid] = 0.f;
    if (tid < 64) {
        int g = tid >> 4;
        float mean = mr[(b * 4 + g) * 2 + 0];
        float rstd = mr[(b * 4 + g) * 2 + 1];
        float s = rstd * gw[tid];
        sc[tid] = s;
        sh[tid] = gb[tid] - mean * s;
    }
    __syncthreads();

    const float* hb = h + (size_t)b * 64 * HWP;
    const int* mb = masks + b * HWP;

    const int p0 = chunk * 512;
    for (int p = p0 + tid; p < p0 + 512; p += 256) {
        int k = mb[p] - 1;
        if (k >= 0) {
            atomicAdd(&s_cnt[k], 1.f);
#pragma unroll
            for (int c = 0; c < 64; c++) {
                float v = fmaxf(fmaf(hb[c * HWP + p], sc[c], sh[c]), 0.f);
                atomicAdd(&s_sums[k * 65 + c], v);
            }
        }
    }
    __syncthreads();

    float* pb = partial + (size_t)(b * 32 + chunk) * (KIDS * 64);
    for (int i = tid; i < KIDS * 64; i += 256) {
        int k = i >> 6, c = i & 63;
        pb[i] = s_sums[k * 65 + c];
    }
    if (tid < KIDS) pcnt[(b * 32 + chunk) * KIDS + tid] = s_cnt[tid];
}

// ---------------- reduce partials + dense heads ----------------
__global__ void heads_kernel(const float* __restrict__ partial, const float* __restrict__ pcnt,
                             const float* __restrict__ wb, const float* __restrict__ bb,
                             const float* __restrict__ wc, const float* __restrict__ bc,
                             float* __restrict__ out)
{
    const int b = blockIdx.x;
    const int k = blockIdx.y;
    const int c = threadIdx.x;

    float s = 0.f;
    for (int ch = 0; ch < 32; ch++)
        s += partial[(size_t)(b * 32 + ch) * (KIDS * 64) + k * 64 + c];
    float cnt = 0.f;
    for (int ch = 0; ch < 32; ch++)
        cnt += pcnt[(b * 32 + ch) * KIDS + k];
    float pooled = s / (cnt + 1e-6f);

    __shared__ float red[64];
#pragma unroll
    for (int o = 0; o < 7; o++) {
        red[c] = pooled * wb[o * 64 + c];
        __syncthreads();
        for (int st = 32; st > 0; st >>= 1) {
            if (c < st) red[c] += red[c + st];
            __syncthreads();
        }
        if (c == 0) out[(b * KIDS + k) * 7 + o] = red[0] + bb[o];
        __syncthreads();
    }
    red[c] = pooled * wc[c];
    __syncthreads();
    for (int st = 32; st > 0; st >>= 1) {
        if (c < st) red[c] += red[c + st];
        __syncthreads();
    }
    if (c == 0) {
        float z = red[0] + bc[0];
        out[BATCH * KIDS * 7 + b * KIDS + k] = 1.f / (1.f + expf(-z));
    }
}

// ---------------- launch ----------------
extern "C" void kernel_launch(void* const* d_in, const int* in_sizes, int n_in,
                              void* d_out, int out_size)
{
    const float* x    = (const float*)d_in[0];
    const int*   masks= (const int*)  d_in[1];
    const float* w1   = (const float*)d_in[2];
    const float* b1   = (const float*)d_in[3];
    const float* g1w  = (const float*)d_in[4];
    const float* g1b  = (const float*)d_in[5];
    const float* w2   = (const float*)d_in[6];
    const float* b2   = (const float*)d_in[7];
    const float* g2w  = (const float*)d_in[8];
    const float* g2b  = (const float*)d_in[9];
    const float* w3   = (const float*)d_in[10];
    const float* b3   = (const float*)d_in[11];
    const float* g3w  = (const float*)d_in[12];
    const float* g3b  = (const float*)d_in[13];
    const float* wb   = (const float*)d_in[14];
    const float* bb   = (const float*)d_in[15];
    const float* wc   = (const float*)d_in[16];
    const float* bc   = (const float*)d_in[17];
    float* out = (float*)d_out;

    float *buf1, *buf2, *buf3, *mr, *gnpart, *partial, *pcnt;
    cudaGetSymbolAddress((void**)&buf1, g_buf1);
    cudaGetSymbolAddress((void**)&buf2, g_buf2);
    cudaGetSymbolAddress((void**)&buf3, g_buf3);
    cudaGetSymbolAddress((void**)&mr, g_mr);
    cudaGetSymbolAddress((void**)&gnpart, g_gnpart);
    cudaGetSymbolAddress((void**)&partial, g_partial);
    cudaGetSymbolAddress((void**)&pcnt, g_pcnt);

    // dynamic smem: (M + 128) * 78 * 4 + GN arrays
    const int SM1 = (128 + 128) * 78 * 4;                 // 79872
    const int SM2 = (128 + 128) * 78 * 4 + 2 * 256 * 4;   // 81920
    const int SM3 = (64 + 128) * 78 * 4 + 2 * 128 * 4;    // 60928
    cudaFuncSetAttribute(conv_mma_kernel<512, 256, false>,
                         cudaFuncAttributeMaxDynamicSharedMemorySize, SM1);
    cudaFuncSetAttribute(conv_mma_kernel<256, 128, true>,
                         cudaFuncAttributeMaxDynamicSharedMemorySize, SM2);
    cudaFuncSetAttribute(conv_mma_kernel<128, 64, true>,
                         cudaFuncAttributeMaxDynamicSharedMemorySize, SM3);

    // layer 1: 512 -> 256
    conv_mma_kernel<512, 256, false><<<dim3(512, 2), 256, SM1>>>(
        x, w1, b1, buf1, nullptr, nullptr, nullptr, 0);
    gn_part_kernel<<<32 * 16, 256>>>(buf1, gnpart, 32, 16);
    gn_final_kernel<<<1, 32>>>(gnpart, mr, 16, 1.f / 524288.f);

    // layer 2: 256 -> 128 (GN1+ReLU fused into B staging)
    conv_mma_kernel<256, 128, true><<<dim3(512, 1), 256, SM2>>>(
        buf1, w2, b2, buf2, mr, g1w, g1b, 8);
    gn_part_kernel<<<16 * 32, 256>>>(buf2, gnpart, 32, 32);
    gn_final_kernel<<<1, 16>>>(gnpart, mr, 32, 1.f / 524288.f);

    // layer 3: 128 -> 64 (GN2+ReLU fused into B staging)
    conv_mma_kernel<128, 64, true><<<dim3(512, 1), 256, SM3>>>(
        buf2, w3, b3, buf3, mr, g2w, g2b, 4);
    gn_part_kernel<<<16 * 32, 256>>>(buf3, gnpart, 16, 32);
    gn_final_kernel<<<1, 16>>>(gnpart, mr, 32, 1.f / 262144.f);

    // pooling (GN3+ReLU fused at read) + heads
    pool_acc_kernel<<<dim3(32, BATCH), 256>>>(buf3, masks, mr, g3w, g3b, partial, pcnt);
    heads_kernel<<<dim3(BATCH, KIDS), 64>>>(partial, pcnt, wb, bb, wc, bc, out);
}

// round 11
// speedup vs baseline: 1.5794x; 1.0686x over previous
#include <cuda_runtime.h>
#include <cstdint>
#include <math.h>

#define HH 128
#define WW 128
#define HWP 16384
#define BATCH 4
#define KIDS 20

// ---------------- scratch (device globals; no allocation) ----------------
__device__ float g_buf1[BATCH * 256 * HWP];   // 67 MB
__device__ float g_buf2[BATCH * 128 * HWP];   // 33.5 MB
__device__ float g_buf3[BATCH * 64 * HWP];    // 16.8 MB
__device__ float g_mr[64];                    // mean/rstd pairs
__device__ float g_gnpart[4096];              // GN partial sums
__device__ float g_partial[BATCH * 32 * KIDS * 64];
__device__ float g_pcnt[BATCH * 32 * KIDS];

// ---------------- tf32 mma (raw fp32 operands; HW truncation) ----------------
__device__ __forceinline__ void mma_tf32(float* c, uint32_t a0, uint32_t a1,
                                         uint32_t a2, uint32_t a3,
                                         uint32_t b0, uint32_t b1) {
    asm volatile("mma.sync.aligned.m16n8k8.row.col.f32.tf32.tf32.f32 "
                 "{%0,%1,%2,%3}, {%4,%5,%6,%7}, {%8,%9}, {%0,%1,%2,%3};"
                 : "+f"(c[0]), "+f"(c[1]), "+f"(c[2]), "+f"(c[3])
                 : "r"(a0), "r"(a1), "r"(a2), "r"(a3), "r"(b0), "r"(b1));
}

// ---------------- conv as tf32 mma.sync implicit GEMM ----------------
// K-MAJOR smem tiles (round-11 change): As[k][row] stride APAD=M+8,
// Bs[k][px] stride BPAD=136. Both strides = 8 (mod 32), so:
//  - fragment lds.32 banks = 8q+g  -> 32 distinct banks, conflict-free
//  - B im2col STS banks = 8k+px    -> conflict-free (px consecutive per warp)
//  - A staging lane->row-major     -> STS banks 8i+row, conflict-free
// Same staged values and same mma order as round 10 -> bit-identical numerics.
template<int CI, int CO, bool GN>
__global__ __launch_bounds__(256, 2)
void conv_mma_kernel(const float* __restrict__ in, const float* __restrict__ wgt,
                     const float* __restrict__ bias, float* __restrict__ out,
                     const float* __restrict__ mr, const float* __restrict__ gw,
                     const float* __restrict__ gb, int Gin)
{
    constexpr int K = CI * 9;
    constexpr int NCHUNK = CI / 8;            // 72 k per chunk
    constexpr int M = (CO < 128) ? CO : 128;
    constexpr int MFRAG = M / 32;
    constexpr int LOG2M = (M == 128) ? 7 : 6;
    constexpr int APAD = M + 8;               // k-major row stride (mod 32 == 8)
    constexpr int BPAD = 136;                 // k-major px stride (mod 32 == 8)
    constexpr int A4 = M * 18;                // float4s of A per chunk

    extern __shared__ char smem[];
    float* As = reinterpret_cast<float*>(smem);       // [72][APAD]
    float* Bs = As + 72 * APAD;                       // [72][BPAD]
    float* scp = Bs + 72 * BPAD;                      // GN scale [CI]
    float* shp = scp + (GN ? CI : 0);

    const int tile = blockIdx.x;
    const int b = tile >> 7;
    const int y = tile & 127;
    const int m0 = blockIdx.y * M;
    const int tid = threadIdx.x;
    const int lane = tid & 31;
    const int g = lane >> 2;
    const int q = lane & 3;
    const int w = tid >> 5;
    const int warpM = w >> 2;
    const int warpN = w & 3;
    const int m0w = warpM * (M / 2);
    const int n0w = warpN * 32;

    if (GN) {
        const int CPG = CI / Gin;
        for (int c = tid; c < CI; c += 256) {
            int gi = c / CPG;
            float mean = mr[(b * Gin + gi) * 2 + 0];
            float rstd = mr[(b * Gin + gi) * 2 + 1];
            float s = rstd * gw[c];
            scp[c] = s;
            shp[c] = gb[c] - mean * s;
        }
    }

    const float* inB = in + (size_t)b * CI * HWP;
    const int px = tid & 127;
    const int khalf = tid >> 7;        // 0/1 -> local channels 0..3 / 4..7

    // hoisted im2col geometry
    const int py[3]  = { (y - 1) * WW, y * WW, (y + 1) * WW };
    const int pxx[3] = { px - 1, px, px + 1 };
    const bool vy[3] = { y > 0, true, y < 127 };
    const bool vx[3] = { px > 0, true, px < 127 };

    // A staging mapping: lane -> row-major (consecutive lanes = consecutive rows)
    const int arow = tid & (M - 1);
    const int ak4base = tid >> LOG2M;
    constexpr int ASTRIDE = 256 >> LOG2M;     // k4 step per iteration

    float acc[MFRAG][4][4];
#pragma unroll
    for (int mi = 0; mi < MFRAG; mi++)
#pragma unroll
        for (int ni = 0; ni < 4; ni++)
#pragma unroll
            for (int j = 0; j < 4; j++) acc[mi][ni][j] = 0.f;

    for (int chunk = 0; chunk < NCHUNK; chunk++) {
        const int kbase = chunk * 72;
        __syncthreads();   // previous compute done before overwrite

        // ---- stage A (weights) K-major: conflict-free STS
#pragma unroll
        for (int it = 0; it < (A4 + 255) / 256; it++) {
            int k4 = ak4base + it * ASTRIDE;
            if ((A4 % 256 == 0) || k4 < 18) {
                float4 v = *reinterpret_cast<const float4*>(
                    wgt + (size_t)(m0 + arow) * K + kbase + k4 * 4);
                float* dst = As + (k4 * 4) * APAD + arow;
                dst[0 * APAD] = v.x;
                dst[1 * APAD] = v.y;
                dst[2 * APAD] = v.z;
                dst[3 * APAD] = v.w;
            }
        }
        // ---- stage B (im2col) K-major: conflict-free STS, compile-time taps
        {
            const int cib = chunk * 8 + khalf * 4;
#pragma unroll
            for (int jc = 0; jc < 4; jc++) {
                const float* pc = inB + (size_t)(cib + jc) * HWP;
                float s = 0.f, h = 0.f;
                if (GN) { s = scp[cib + jc]; h = shp[cib + jc]; }
                const int kb = (khalf * 4 + jc) * 9;
#pragma unroll
                for (int t = 0; t < 9; t++) {
                    const int dy = t / 3;          // compile-time 0..2
                    const int dx = t - dy * 3;     // compile-time 0..2
                    float v = 0.f;
                    if (vy[dy] && vx[dx]) {
                        v = pc[py[dy] + pxx[dx]];
                        if (GN) v = fmaxf(fmaf(v, s, h), 0.f);
                    }
                    Bs[(kb + t) * BPAD + px] = v;
                }
            }
        }
        __syncthreads();

        // ---- compute: 9 k-steps of m16n8k8, conflict-free scalar fragment loads
#pragma unroll
        for (int ks = 0; ks < 9; ks++) {
            const int k0 = 8 * ks + q;
            uint32_t af[MFRAG][4];
#pragma unroll
            for (int mi = 0; mi < MFRAG; mi++) {
                int row = m0w + mi * 16 + g;
                af[mi][0] = __float_as_uint(As[k0 * APAD + row]);
                af[mi][1] = __float_as_uint(As[k0 * APAD + row + 8]);
                af[mi][2] = __float_as_uint(As[(k0 + 4) * APAD + row]);
                af[mi][3] = __float_as_uint(As[(k0 + 4) * APAD + row + 8]);
            }
#pragma unroll
            for (int ni = 0; ni < 4; ni++) {
                int pxn = n0w + ni * 8 + g;
                uint32_t b0 = __float_as_uint(Bs[k0 * BPAD + pxn]);
                uint32_t b1 = __float_as_uint(Bs[(k0 + 4) * BPAD + pxn]);
#pragma unroll
                for (int mi = 0; mi < MFRAG; mi++)
                    mma_tf32(acc[mi][ni], af[mi][0], af[mi][1], af[mi][2], af[mi][3], b0, b1);
            }
        }
    }

    // ---- epilogue: +bias, store NCHW as float2 pairs
#pragma unroll
    for (int mi = 0; mi < MFRAG; mi++) {
        int colo = m0 + m0w + mi * 16 + g;
        int cohi = colo + 8;
        float blo = bias[colo];
        float bhi = bias[cohi];
        float* dlo = out + (((size_t)(b * CO + colo)) * HH + y) * WW;
        float* dhi = out + (((size_t)(b * CO + cohi)) * HH + y) * WW;
#pragma unroll
        for (int ni = 0; ni < 4; ni++) {
            int x0 = n0w + ni * 8 + 2 * q;
            float2 v0 = make_float2(acc[mi][ni][0] + blo, acc[mi][ni][1] + blo);
            float2 v1 = make_float2(acc[mi][ni][2] + bhi, acc[mi][ni][3] + bhi);
            *reinterpret_cast<float2*>(dlo + x0) = v0;
            *reinterpret_cast<float2*>(dhi + x0) = v1;
        }
    }
}

// ---------------- GroupNorm statistics: partial pass ----------------
__global__ void gn_part_kernel(const float* __restrict__ x, float* __restrict__ part,
                               int Cg, int SL)
{
    const int bg = blockIdx.x / SL;
    const int sl = blockIdx.x % SL;
    const size_t n = (size_t)Cg * HWP;
    const size_t cn = n / SL;
    const float4* p = reinterpret_cast<const float4*>(x + (size_t)bg * n + (size_t)sl * cn);
    const int n4 = (int)(cn >> 2);

    float s = 0.f, ss = 0.f;
    for (int i = threadIdx.x; i < n4; i += 256) {
        float4 v = p[i];
        s  += v.x + v.y + v.z + v.w;
        ss += v.x * v.x + v.y * v.y + v.z * v.z + v.w * v.w;
    }
    __shared__ float sh_s[256], sh_ss[256];
    sh_s[threadIdx.x] = s;
    sh_ss[threadIdx.x] = ss;
    __syncthreads();
    for (int st = 128; st > 0; st >>= 1) {
        if ((int)threadIdx.x < st) {
            sh_s[threadIdx.x]  += sh_s[threadIdx.x + st];
            sh_ss[threadIdx.x] += sh_ss[threadIdx.x + st];
        }
        __syncthreads();
    }
    if (threadIdx.x == 0) {
        part[blockIdx.x * 2 + 0] = sh_s[0];
        part[blockIdx.x * 2 + 1] = sh_ss[0];
    }
}

// ---------------- GroupNorm statistics: final reduce ----------------
__global__ void gn_final_kernel(const float* __restrict__ part, float* __restrict__ mr,
                                int SL, float inv_n)
{
    const int bg = threadIdx.x;
    float s = 0.f, ss = 0.f;
    for (int i = 0; i < SL; i++) {
        s  += part[(bg * SL + i) * 2 + 0];
        ss += part[(bg * SL + i) * 2 + 1];
    }
    float mean = s * inv_n;
    float var = ss * inv_n - mean * mean;
    mr[bg * 2 + 0] = mean;
    mr[bg * 2 + 1] = rsqrtf(var + 1e-5f);
}

// ---------------- masked segment pooling (GN3+ReLU fused at read) ----------------
__global__ void pool_acc_kernel(const float* __restrict__ h, const int* __restrict__ masks,
                                const float* __restrict__ mr, const float* __restrict__ gw,
                                const float* __restrict__ gb,
                                float* __restrict__ partial, float* __restrict__ pcnt)
{
    const int b = blockIdx.y;
    const int chunk = blockIdx.x;
    const int tid = threadIdx.x;

    __shared__ float s_sums[KIDS * 65];
    __shared__ float s_cnt[KIDS];
    __shared__ float sc[64], sh[64];
    for (int i = tid; i < KIDS * 65; i += 256) s_sums[i] = 0.f;
    if (tid < KIDS) s_cnt[tid] = 0.f;
    if (tid < 64) {
        int g = tid >> 4;
        float mean = mr[(b * 4 + g) * 2 + 0];
        float rstd = mr[(b * 4 + g) * 2 + 1];
        float s = rstd * gw[tid];
        sc[tid] = s;
        sh[tid] = gb[tid] - mean * s;
    }
    __syncthreads();

    const float* hb = h + (size_t)b * 64 * HWP;
    const int* mb = masks + b * HWP;

    const int p0 = chunk * 512;
    for (int p = p0 + tid; p < p0 + 512; p += 256) {
        int k = mb[p] - 1;
        if (k >= 0) {
            atomicAdd(&s_cnt[k], 1.f);
#pragma unroll
            for (int c = 0; c < 64; c++) {
                float v = fmaxf(fmaf(hb[c * HWP + p], sc[c], sh[c]), 0.f);
                atomicAdd(&s_sums[k * 65 + c], v);
            }
        }
    }
    __syncthreads();

    float* pb = partial + (size_t)(b * 32 + chunk) * (KIDS * 64);
    for (int i = tid; i < KIDS * 64; i += 256) {
        int k = i >> 6, c = i & 63;
        pb[i] = s_sums[k * 65 + c];
    }
    if (tid < KIDS) pcnt[(b * 32 + chunk) * KIDS + tid] = s_cnt[tid];
}

// ---------------- reduce partials + dense heads ----------------
__global__ void heads_kernel(const float* __restrict__ partial, const float* __restrict__ pcnt,
                             const float* __restrict__ wb, const float* __restrict__ bb,
                             const float* __restrict__ wc, const float* __restrict__ bc,
                             float* __restrict__ out)
{
    const int b = blockIdx.x;
    const int k = blockIdx.y;
    const int c = threadIdx.x;

    float s = 0.f;
    for (int ch = 0; ch < 32; ch++)
        s += partial[(size_t)(b * 32 + ch) * (KIDS * 64) + k * 64 + c];
    float cnt = 0.f;
    for (int ch = 0; ch < 32; ch++)
        cnt += pcnt[(b * 32 + ch) * KIDS + k];
    float pooled = s / (cnt + 1e-6f);

    __shared__ float red[64];
#pragma unroll
    for (int o = 0; o < 7; o++) {
        red[c] = pooled * wb[o * 64 + c];
        __syncthreads();
        for (int st = 32; st > 0; st >>= 1) {
            if (c < st) red[c] += red[c + st];
            __syncthreads();
        }
        if (c == 0) out[(b * KIDS + k) * 7 + o] = red[0] + bb[o];
        __syncthreads();
    }
    red[c] = pooled * wc[c];
    __syncthreads();
    for (int st = 32; st > 0; st >>= 1) {
        if (c < st) red[c] += red[c + st];
        __syncthreads();
    }
    if (c == 0) {
        float z = red[0] + bc[0];
        out[BATCH * KIDS * 7 + b * KIDS + k] = 1.f / (1.f + expf(-z));
    }
}

// ---------------- launch ----------------
extern "C" void kernel_launch(void* const* d_in, const int* in_sizes, int n_in,
                              void* d_out, int out_size)
{
    const float* x    = (const float*)d_in[0];
    const int*   masks= (const int*)  d_in[1];
    const float* w1   = (const float*)d_in[2];
    const float* b1   = (const float*)d_in[3];
    const float* g1w  = (const float*)d_in[4];
    const float* g1b  = (const float*)d_in[5];
    const float* w2   = (const float*)d_in[6];
    const float* b2   = (const float*)d_in[7];
    const float* g2w  = (const float*)d_in[8];
    const float* g2b  = (const float*)d_in[9];
    const float* w3   = (const float*)d_in[10];
    const float* b3   = (const float*)d_in[11];
    const float* g3w  = (const float*)d_in[12];
    const float* g3b  = (const float*)d_in[13];
    const float* wb   = (const float*)d_in[14];
    const float* bb   = (const float*)d_in[15];
    const float* wc   = (const float*)d_in[16];
    const float* bc   = (const float*)d_in[17];
    float* out = (float*)d_out;

    float *buf1, *buf2, *buf3, *mr, *gnpart, *partial, *pcnt;
    cudaGetSymbolAddress((void**)&buf1, g_buf1);
    cudaGetSymbolAddress((void**)&buf2, g_buf2);
    cudaGetSymbolAddress((void**)&buf3, g_buf3);
    cudaGetSymbolAddress((void**)&mr, g_mr);
    cudaGetSymbolAddress((void**)&gnpart, g_gnpart);
    cudaGetSymbolAddress((void**)&partial, g_partial);
    cudaGetSymbolAddress((void**)&pcnt, g_pcnt);

    // dynamic smem: 72*(APAD + BPAD)*4 + GN arrays
    const int SM1 = 72 * (136 + 136) * 4;                  // 78336
    const int SM2 = 72 * (136 + 136) * 4 + 2 * 256 * 4;    // 80384
    const int SM3 = 72 * (72 + 136) * 4 + 2 * 128 * 4;     // 60928
    cudaFuncSetAttribute(conv_mma_kernel<512, 256, false>,
                         cudaFuncAttributeMaxDynamicSharedMemorySize, SM1);
    cudaFuncSetAttribute(conv_mma_kernel<256, 128, true>,
                         cudaFuncAttributeMaxDynamicSharedMemorySize, SM2);
    cudaFuncSetAttribute(conv_mma_kernel<128, 64, true>,
                         cudaFuncAttributeMaxDynamicSharedMemorySize, SM3);

    // layer 1: 512 -> 256
    conv_mma_kernel<512, 256, false><<<dim3(512, 2), 256, SM1>>>(
        x, w1, b1, buf1, nullptr, nullptr, nullptr, 0);
    gn_part_kernel<<<32 * 16, 256>>>(buf1, gnpart, 32, 16);
    gn_final_kernel<<<1, 32>>>(gnpart, mr, 16, 1.f / 524288.f);

    // layer 2: 256 -> 128 (GN1+ReLU fused into B staging)
    conv_mma_kernel<256, 128, true><<<dim3(512, 1), 256, SM2>>>(
        buf1, w2, b2, buf2, mr, g1w, g1b, 8);
    gn_part_kernel<<<16 * 32, 256>>>(buf2, gnpart, 32, 32);
    gn_final_kernel<<<1, 16>>>(gnpart, mr, 32, 1.f / 524288.f);

    // layer 3: 128 -> 64 (GN2+ReLU fused into B staging)
    conv_mma_kernel<128, 64, true><<<dim3(512, 1), 256, SM3>>>(
        buf2, w3, b3, buf3, mr, g2w, g2b, 4);
    gn_part_kernel<<<16 * 32, 256>>>(buf3, gnpart, 16, 32);
    gn_final_kernel<<<1, 16>>>(gnpart, mr, 32, 1.f / 262144.f);

    // pooling (GN3+ReLU fused at read) + heads
    pool_acc_kernel<<<dim3(32, BATCH), 256>>>(buf3, masks, mr, g3w, g3b, partial, pcnt);
    heads_kernel<<<dim3(BATCH, KIDS), 64>>>(partial, pcnt, wb, bb, wc, bc, out);
}

// round 12
// speedup vs baseline: 1.7110x; 1.0834x over previous
#include <cuda_runtime.h>
#include <cstdint>
#include <math.h>

#define HH 128
#define WW 128
#define HWP 16384
#define BATCH 4
#define KIDS 20

// ---------------- scratch (device globals; no allocation) ----------------
__device__ float g_buf1[BATCH * 256 * HWP];   // 67 MB
__device__ float g_buf2[BATCH * 128 * HWP];   // 33.5 MB
__device__ float g_buf3[BATCH * 64 * HWP];    // 16.8 MB
__device__ float g_mr[64];                    // mean/rstd pairs
__device__ float g_gnpart[4096];              // GN partial sums
__device__ float g_partial[BATCH * 32 * KIDS * 64];
__device__ float g_pcnt[BATCH * 32 * KIDS];

// ---------------- tf32 mma (raw fp32 operands; HW truncation) ----------------
__device__ __forceinline__ void mma_tf32(float* c, uint32_t a0, uint32_t a1,
                                         uint32_t a2, uint32_t a3,
                                         uint32_t b0, uint32_t b1) {
    asm volatile("mma.sync.aligned.m16n8k8.row.col.f32.tf32.tf32.f32 "
                 "{%0,%1,%2,%3}, {%4,%5,%6,%7}, {%8,%9}, {%0,%1,%2,%3};"
                 : "+f"(c[0]), "+f"(c[1]), "+f"(c[2]), "+f"(c[3])
                 : "r"(a0), "r"(a1), "r"(a2), "r"(a3), "r"(b0), "r"(b1));
}

// ---------------- conv as tf32 mma.sync implicit GEMM ----------------
// Round-12 change: B is stored as RAW input rows, not materialized im2col.
// Braw[8 ch][3 dy][136]: data floats at [4..131] (x = idx-4), guard zeros at
// [3] and [132] (for x=-1 / x=128), zeroed once before the chunk loop.
// Staging = cooperative float4 row copy (3 float4 per thread per chunk,
// ~12x fewer B LSU ops than materialized im2col). The mma B operand reads
// the shifted view via a per-thread offset table off(k)=cloc*408+dy*136+3+dx.
// Invalid dy rows are stored as zeros. Values and mma order are bit-identical
// to round 11. A side (k-major As, conflict-free) unchanged.
template<int CI, int CO, bool GN>
__global__ __launch_bounds__(256, 2)
void conv_mma_kernel(const float* __restrict__ in, const float* __restrict__ wgt,
                     const float* __restrict__ bias, float* __restrict__ out,
                     const float* __restrict__ mr, const float* __restrict__ gw,
                     const float* __restrict__ gb, int Gin)
{
    constexpr int K = CI * 9;
    constexpr int NCHUNK = CI / 8;            // 72 k per chunk
    constexpr int M = (CO < 128) ? CO : 128;
    constexpr int MFRAG = M / 32;
    constexpr int LOG2M = (M == 128) ? 7 : 6;
    constexpr int APAD = M + 8;               // k-major row stride (mod 32 == 8)
    constexpr int RPAD = 136;                 // Braw row stride (mod 32 == 8)
    constexpr int A4 = M * 18;                // float4s of A per chunk

    extern __shared__ char smem[];
    float* As = reinterpret_cast<float*>(smem);       // [72][APAD]
    float* Braw = As + 72 * APAD;                     // [24][RPAD]
    float* scp = Braw + 24 * RPAD;                    // GN scale [CI]
    float* shp = scp + (GN ? CI : 0);

    const int tile = blockIdx.x;
    const int b = tile >> 7;
    const int y = tile & 127;
    const int m0 = blockIdx.y * M;
    const int tid = threadIdx.x;
    const int lane = tid & 31;
    const int g = lane >> 2;
    const int q = lane & 3;
    const int w = tid >> 5;
    const int warpM = w >> 2;
    const int warpN = w & 3;
    const int m0w = warpM * (M / 2);
    const int n0w = warpN * 32;

    if (GN) {
        const int CPG = CI / Gin;
        for (int c = tid; c < CI; c += 256) {
            int gi = c / CPG;
            float mean = mr[(b * Gin + gi) * 2 + 0];
            float rstd = mr[(b * Gin + gi) * 2 + 1];
            float s = rstd * gw[c];
            scp[c] = s;
            shp[c] = gb[c] - mean * s;
        }
    }
    // zero the guard words once (slots [0..3] and [132..135] of each row)
    for (int i = tid; i < 24 * 8; i += 256) {
        int row = i >> 3;
        int sl = i & 7;
        Braw[row * RPAD + (sl < 4 ? sl : 128 + sl)] = 0.f;
    }

    const float* inB = in + (size_t)b * CI * HWP;

    // per-thread B fragment offset table (constant across chunks)
    int offA9[9], offB9[9];
#pragma unroll
    for (int ks = 0; ks < 9; ks++) {
        int kA = 8 * ks + q;
        int cA = kA / 9, rA = kA - 9 * cA;
        int dyA = rA / 3, dxA = rA - 3 * dyA;
        offA9[ks] = cA * (3 * RPAD) + dyA * RPAD + 3 + dxA;
        int kB = kA + 4;
        int cB = kB / 9, rB = kB - 9 * cB;
        int dyB = rB / 3, dxB = rB - 3 * dyB;
        offB9[ks] = cB * (3 * RPAD) + dyB * RPAD + 3 + dxB;
    }

    // A staging mapping: lane -> row-major
    const int arow = tid & (M - 1);
    const int ak4base = tid >> LOG2M;
    constexpr int ASTRIDE = 256 >> LOG2M;

    float acc[MFRAG][4][4];
#pragma unroll
    for (int mi = 0; mi < MFRAG; mi++)
#pragma unroll
        for (int ni = 0; ni < 4; ni++)
#pragma unroll
            for (int j = 0; j < 4; j++) acc[mi][ni][j] = 0.f;

    for (int chunk = 0; chunk < NCHUNK; chunk++) {
        const int kbase = chunk * 72;
        __syncthreads();   // previous compute done before overwrite

        // ---- stage A (weights) K-major: conflict-free STS
#pragma unroll
        for (int it = 0; it < (A4 + 255) / 256; it++) {
            int k4 = ak4base + it * ASTRIDE;
            if ((A4 % 256 == 0) || k4 < 18) {
                float4 v = *reinterpret_cast<const float4*>(
                    wgt + (size_t)(m0 + arow) * K + kbase + k4 * 4);
                float* dst = As + (k4 * 4) * APAD + arow;
                dst[0 * APAD] = v.x;
                dst[1 * APAD] = v.y;
                dst[2 * APAD] = v.z;
                dst[3 * APAD] = v.w;
            }
        }
        // ---- stage B raw rows: 24 rows x 32 float4, GN+ReLU fused per component
        {
            const int cib = chunk * 8;
#pragma unroll
            for (int i = 0; i < 3; i++) {
                int idx = tid + i * 256;          // 0..767
                int row = idx >> 5;               // 0..23
                int j4 = idx & 31;                // 0..31
                int cloc = row / 3;
                int dy = row - 3 * cloc;
                int yy = y + dy - 1;
                float4 v = make_float4(0.f, 0.f, 0.f, 0.f);
                if ((unsigned)yy < 128u) {
                    v = *reinterpret_cast<const float4*>(
                        inB + (size_t)(cib + cloc) * HWP + yy * WW + 4 * j4);
                    if (GN) {
                        float s = scp[cib + cloc], h = shp[cib + cloc];
                        v.x = fmaxf(fmaf(v.x, s, h), 0.f);
                        v.y = fmaxf(fmaf(v.y, s, h), 0.f);
                        v.z = fmaxf(fmaf(v.z, s, h), 0.f);
                        v.w = fmaxf(fmaf(v.w, s, h), 0.f);
                    }
                }
                *reinterpret_cast<float4*>(Braw + row * RPAD + 4 + 4 * j4) = v;
            }
        }
        __syncthreads();

        // ---- compute: 9 k-steps of m16n8k8
#pragma unroll
        for (int ks = 0; ks < 9; ks++) {
            const int k0 = 8 * ks + q;
            uint32_t af[MFRAG][4];
#pragma unroll
            for (int mi = 0; mi < MFRAG; mi++) {
                int row = m0w + mi * 16 + g;
                af[mi][0] = __float_as_uint(As[k0 * APAD + row]);
                af[mi][1] = __float_as_uint(As[k0 * APAD + row + 8]);
                af[mi][2] = __float_as_uint(As[(k0 + 4) * APAD + row]);
                af[mi][3] = __float_as_uint(As[(k0 + 4) * APAD + row + 8]);
            }
#pragma unroll
            for (int ni = 0; ni < 4; ni++) {
                int pxn = n0w + ni * 8 + g;
                uint32_t b0 = __float_as_uint(Braw[offA9[ks] + pxn]);
                uint32_t b1 = __float_as_uint(Braw[offB9[ks] + pxn]);
#pragma unroll
                for (int mi = 0; mi < MFRAG; mi++)
                    mma_tf32(acc[mi][ni], af[mi][0], af[mi][1], af[mi][2], af[mi][3], b0, b1);
            }
        }
    }

    // ---- epilogue: +bias, store NCHW as float2 pairs
#pragma unroll
    for (int mi = 0; mi < MFRAG; mi++) {
        int colo = m0 + m0w + mi * 16 + g;
        int cohi = colo + 8;
        float blo = bias[colo];
        float bhi = bias[cohi];
        float* dlo = out + (((size_t)(b * CO + colo)) * HH + y) * WW;
        float* dhi = out + (((size_t)(b * CO + cohi)) * HH + y) * WW;
#pragma unroll
        for (int ni = 0; ni < 4; ni++) {
            int x0 = n0w + ni * 8 + 2 * q;
            float2 v0 = make_float2(acc[mi][ni][0] + blo, acc[mi][ni][1] + blo);
            float2 v1 = make_float2(acc[mi][ni][2] + bhi, acc[mi][ni][3] + bhi);
            *reinterpret_cast<float2*>(dlo + x0) = v0;
            *reinterpret_cast<float2*>(dhi + x0) = v1;
        }
    }
}

// ---------------- GroupNorm statistics: partial pass ----------------
__global__ void gn_part_kernel(const float* __restrict__ x, float* __restrict__ part,
                               int Cg, int SL)
{
    const int bg = blockIdx.x / SL;
    const int sl = blockIdx.x % SL;
    const size_t n = (size_t)Cg * HWP;
    const size_t cn = n / SL;
    const float4* p = reinterpret_cast<const float4*>(x + (size_t)bg * n + (size_t)sl * cn);
    const int n4 = (int)(cn >> 2);

    float s = 0.f, ss = 0.f;
    for (int i = threadIdx.x; i < n4; i += 256) {
        float4 v = p[i];
        s  += v.x + v.y + v.z + v.w;
        ss += v.x * v.x + v.y * v.y + v.z * v.z + v.w * v.w;
    }
    __shared__ float sh_s[256], sh_ss[256];
    sh_s[threadIdx.x] = s;
    sh_ss[threadIdx.x] = ss;
    __syncthreads();
    for (int st = 128; st > 0; st >>= 1) {
        if ((int)threadIdx.x < st) {
            sh_s[threadIdx.x]  += sh_s[threadIdx.x + st];
            sh_ss[threadIdx.x] += sh_ss[threadIdx.x + st];
        }
        __syncthreads();
    }
    if (threadIdx.x == 0) {
        part[blockIdx.x * 2 + 0] = sh_s[0];
        part[blockIdx.x * 2 + 1] = sh_ss[0];
    }
}

// ---------------- GroupNorm statistics: final reduce ----------------
__global__ void gn_final_kernel(const float* __restrict__ part, float* __restrict__ mr,
                                int SL, float inv_n)
{
    const int bg = threadIdx.x;
    float s = 0.f, ss = 0.f;
    for (int i = 0; i < SL; i++) {
        s  += part[(bg * SL + i) * 2 + 0];
        ss += part[(bg * SL + i) * 2 + 1];
    }
    float mean = s * inv_n;
    float var = ss * inv_n - mean * mean;
    mr[bg * 2 + 0] = mean;
    mr[bg * 2 + 1] = rsqrtf(var + 1e-5f);
}

// ---------------- masked segment pooling (GN3+ReLU fused at read) ----------------
__global__ void pool_acc_kernel(const float* __restrict__ h, const int* __restrict__ masks,
                                const float* __restrict__ mr, const float* __restrict__ gw,
                                const float* __restrict__ gb,
                                float* __restrict__ partial, float* __restrict__ pcnt)
{
    const int b = blockIdx.y;
    const int chunk = blockIdx.x;
    const int tid = threadIdx.x;

    __shared__ float s_sums[KIDS * 65];
    __shared__ float s_cnt[KIDS];
    __shared__ float sc[64], sh[64];
    for (int i = tid; i < KIDS * 65; i += 256) s_sums[i] = 0.f;
    if (tid < KIDS) s_cnt[tid] = 0.f;
    if (tid < 64) {
        int g = tid >> 4;
        float mean = mr[(b * 4 + g) * 2 + 0];
        float rstd = mr[(b * 4 + g) * 2 + 1];
        float s = rstd * gw[tid];
        sc[tid] = s;
        sh[tid] = gb[tid] - mean * s;
    }
    __syncthreads();

    const float* hb = h + (size_t)b * 64 * HWP;
    const int* mb = masks + b * HWP;

    const int p0 = chunk * 512;
    for (int p = p0 + tid; p < p0 + 512; p += 256) {
        int k = mb[p] - 1;
        if (k >= 0) {
            atomicAdd(&s_cnt[k], 1.f);
#pragma unroll
            for (int c = 0; c < 64; c++) {
                float v = fmaxf(fmaf(hb[c * HWP + p], sc[c], sh[c]), 0.f);
                atomicAdd(&s_sums[k * 65 + c], v);
            }
        }
    }
    __syncthreads();

    float* pb = partial + (size_t)(b * 32 + chunk) * (KIDS * 64);
    for (int i = tid; i < KIDS * 64; i += 256) {
        int k = i >> 6, c = i & 63;
        pb[i] = s_sums[k * 65 + c];
    }
    if (tid < KIDS) pcnt[(b * 32 + chunk) * KIDS + tid] = s_cnt[tid];
}

// ---------------- reduce partials + dense heads ----------------
__global__ void heads_kernel(const float* __restrict__ partial, const float* __restrict__ pcnt,
                             const float* __restrict__ wb, const float* __restrict__ bb,
                             const float* __restrict__ wc, const float* __restrict__ bc,
                             float* __restrict__ out)
{
    const int b = blockIdx.x;
    const int k = blockIdx.y;
    const int c = threadIdx.x;

    float s = 0.f;
    for (int ch = 0; ch < 32; ch++)
        s += partial[(size_t)(b * 32 + ch) * (KIDS * 64) + k * 64 + c];
    float cnt = 0.f;
    for (int ch = 0; ch < 32; ch++)
        cnt += pcnt[(b * 32 + ch) * KIDS + k];
    float pooled = s / (cnt + 1e-6f);

    __shared__ float red[64];
#pragma unroll
    for (int o = 0; o < 7; o++) {
        red[c] = pooled * wb[o * 64 + c];
        __syncthreads();
        for (int st = 32; st > 0; st >>= 1) {
            if (c < st) red[c] += red[c + st];
            __syncthreads();
        }
        if (c == 0) out[(b * KIDS + k) * 7 + o] = red[0] + bb[o];
        __syncthreads();
    }
    red[c] = pooled * wc[c];
    __syncthreads();
    for (int st = 32; st > 0; st >>= 1) {
        if (c < st) red[c] += red[c + st];
        __syncthreads();
    }
    if (c == 0) {
        float z = red[0] + bc[0];
        out[BATCH * KIDS * 7 + b * KIDS + k] = 1.f / (1.f + expf(-z));
    }
}

// ---------------- launch ----------------
extern "C" void kernel_launch(void* const* d_in, const int* in_sizes, int n_in,
                              void* d_out, int out_size)
{
    const float* x    = (const float*)d_in[0];
    const int*   masks= (const int*)  d_in[1];
    const float* w1   = (const float*)d_in[2];
    const float* b1   = (const float*)d_in[3];
    const float* g1w  = (const float*)d_in[4];
    const float* g1b  = (const float*)d_in[5];
    const float* w2   = (const float*)d_in[6];
    const float* b2   = (const float*)d_in[7];
    const float* g2w  = (const float*)d_in[8];
    const float* g2b  = (const float*)d_in[9];
    const float* w3   = (const float*)d_in[10];
    const float* b3   = (const float*)d_in[11];
    const float* g3w  = (const float*)d_in[12];
    const float* g3b  = (const float*)d_in[13];
    const float* wb   = (const float*)d_in[14];
    const float* bb   = (const float*)d_in[15];
    const float* wc   = (const float*)d_in[16];
    const float* bc   = (const float*)d_in[17];
    float* out = (float*)d_out;

    float *buf1, *buf2, *buf3, *mr, *gnpart, *partial, *pcnt;
    cudaGetSymbolAddress((void**)&buf1, g_buf1);
    cudaGetSymbolAddress((void**)&buf2, g_buf2);
    cudaGetSymbolAddress((void**)&buf3, g_buf3);
    cudaGetSymbolAddress((void**)&mr, g_mr);
    cudaGetSymbolAddress((void**)&gnpart, g_gnpart);
    cudaGetSymbolAddress((void**)&partial, g_partial);
    cudaGetSymbolAddress((void**)&pcnt, g_pcnt);

    // dynamic smem: 72*APAD*4 + 24*136*4 + GN arrays
    const int SM1 = 72 * 136 * 4 + 24 * 136 * 4;                 // 52224
    const int SM2 = 72 * 136 * 4 + 24 * 136 * 4 + 2 * 256 * 4;   // 54272
    const int SM3 = 72 * 72 * 4 + 24 * 136 * 4 + 2 * 128 * 4;    // 34816
    cudaFuncSetAttribute(conv_mma_kernel<512, 256, false>,
                         cudaFuncAttributeMaxDynamicSharedMemorySize, SM1);
    cudaFuncSetAttribute(conv_mma_kernel<256, 128, true>,
                         cudaFuncAttributeMaxDynamicSharedMemorySize, SM2);
    cudaFuncSetAttribute(conv_mma_kernel<128, 64, true>,
                         cudaFuncAttributeMaxDynamicSharedMemorySize, SM3);

    // layer 1: 512 -> 256
    conv_mma_kernel<512, 256, false><<<dim3(512, 2), 256, SM1>>>(
        x, w1, b1, buf1, nullptr, nullptr, nullptr, 0);
    gn_part_kernel<<<32 * 16, 256>>>(buf1, gnpart, 32, 16);
    gn_final_kernel<<<1, 32>>>(gnpart, mr, 16, 1.f / 524288.f);

    // layer 2: 256 -> 128 (GN1+ReLU fused into B staging)
    conv_mma_kernel<256, 128, true><<<dim3(512, 1), 256, SM2>>>(
        buf1, w2, b2, buf2, mr, g1w, g1b, 8);
    gn_part_kernel<<<16 * 32, 256>>>(buf2, gnpart, 32, 32);
    gn_final_kernel<<<1, 16>>>(gnpart, mr, 32, 1.f / 524288.f);

    // layer 3: 128 -> 64 (GN2+ReLU fused into B staging)
    conv_mma_kernel<128, 64, true><<<dim3(512, 1), 256, SM3>>>(
        buf2, w3, b3, buf3, mr, g2w, g2b, 4);
    gn_part_kernel<<<16 * 32, 256>>>(buf3, gnpart, 16, 32);
    gn_final_kernel<<<1, 16>>>(gnpart, mr, 32, 1.f / 262144.f);

    // pooling (GN3+ReLU fused at read) + heads
    pool_acc_kernel<<<dim3(32, BATCH), 256>>>(buf3, masks, mr, g3w, g3b, partial, pcnt);
    heads_kernel<<<dim3(BATCH, KIDS), 64>>>(partial, pcnt, wb, bb, wc, bc, out);
}

// round 14
// speedup vs baseline: 2.0943x; 1.2240x over previous
#include <cuda_runtime.h>
#include <cstdint>
#include <math.h>

#define HH 128
#define WW 128
#define HWP 16384
#define BATCH 4
#define KIDS 20

// ---------------- scratch (device globals; no allocation) ----------------
__device__ float g_buf1[BATCH * 256 * HWP];   // 67 MB
__device__ float g_buf2[BATCH * 128 * HWP];   // 33.5 MB
__device__ float g_buf3[BATCH * 64 * HWP];    // 16.8 MB
__device__ float g_mr[64];                    // mean/rstd pairs
__device__ float g_gnpart[4096];              // GN partial sums
__device__ float g_partial[BATCH * 32 * KIDS * 64];
__device__ float g_pcnt[BATCH * 32 * KIDS];

// ---------------- fp16 helpers ----------------
// pack two fp32 into f16x2 (RNE): lo = first arg (low half), hi = second arg
__device__ __forceinline__ uint32_t pack_f16(float lo, float hi) {
    uint32_t r;
    asm("cvt.rn.f16x2.f32 %0, %1, %2;" : "=r"(r) : "f"(hi), "f"(lo));
    return r;
}
__device__ __forceinline__ void mma_f16(float* c, uint32_t a0, uint32_t a1,
                                        uint32_t a2, uint32_t a3,
                                        uint32_t b0, uint32_t b1) {
    asm volatile("mma.sync.aligned.m16n8k16.row.col.f32.f16.f16.f32 "
                 "{%0,%1,%2,%3}, {%4,%5,%6,%7}, {%8,%9}, {%0,%1,%2,%3};"
                 : "+f"(c[0]), "+f"(c[1]), "+f"(c[2]), "+f"(c[3])
                 : "r"(a0), "r"(a1), "r"(a2), "r"(a3), "r"(b0), "r"(b1));
}

// ---------------- conv as fp16 mma.sync implicit GEMM ----------------
// Round-14: round-13 machinery (proved layout-correct) with fp16 operands
// instead of bf16: 11-bit mantissa = tf32-class precision, 2 B/element,
// k=16 per HMMA. fp32 accumulate. Chunk = 16 channels x 9 taps = 144 k
// = 9 k16-steps. smem holds PACKED k-pairs (k2 = k/2), k2-major:
//   As2[k2][row] stride APAD2=M+8 (mod 32 == 8)  -> conflict-free
//   Bs2[k2][px]  stride BPAD2=136  (mod 32 == 8) -> conflict-free
// GN+ReLU fused into B staging, applied ONLY in-bounds (fp32 math, then pack).
template<int CI, int CO, bool GN>
__global__ __launch_bounds__(256, 2)
void conv_mma_kernel(const float* __restrict__ in, const float* __restrict__ wgt,
                     const float* __restrict__ bias, float* __restrict__ out,
                     const float* __restrict__ mr, const float* __restrict__ gw,
                     const float* __restrict__ gb, int Gin)
{
    constexpr int K = CI * 9;
    constexpr int NCHUNK = CI / 16;           // 144 k per chunk
    constexpr int M = (CO < 128) ? CO : 128;
    constexpr int MFRAG = M / 32;
    constexpr int LOG2M = (M == 128) ? 7 : 6;
    constexpr int APAD2 = M + 8;              // k2-major row stride (mod 32 == 8)
    constexpr int BPAD2 = 136;                // k2-major px stride (mod 32 == 8)
    constexpr int A4 = M * 36;                // float4s of A per chunk (144 k)

    extern __shared__ char smem[];
    uint32_t* As2 = reinterpret_cast<uint32_t*>(smem);    // [72][APAD2]
    uint32_t* Bs2 = As2 + 72 * APAD2;                     // [72][BPAD2]
    float* scp = reinterpret_cast<float*>(Bs2 + 72 * BPAD2);   // GN scale [CI]
    float* shp = scp + (GN ? CI : 0);

    const int tile = blockIdx.x;
    const int b = tile >> 7;
    const int y = tile & 127;
    const int m0 = blockIdx.y * M;
    const int tid = threadIdx.x;
    const int lane = tid & 31;
    const int g = lane >> 2;
    const int q = lane & 3;
    const int w = tid >> 5;
    const int warpM = w >> 2;
    const int warpN = w & 3;
    const int m0w = warpM * (M / 2);
    const int n0w = warpN * 32;

    if (GN) {
        const int CPG = CI / Gin;
        for (int c = tid; c < CI; c += 256) {
            int gi = c / CPG;
            float mean = mr[(b * Gin + gi) * 2 + 0];
            float rstd = mr[(b * Gin + gi) * 2 + 1];
            float s = rstd * gw[c];
            scp[c] = s;
            shp[c] = gb[c] - mean * s;
        }
    }

    const float* inB = in + (size_t)b * CI * HWP;
    const int px = tid & 127;
    const int khalf = tid >> 7;        // 0/1 -> channels 0..7 / 8..15 of chunk

    // hoisted im2col geometry
    const int py[3]  = { (y - 1) * WW, y * WW, (y + 1) * WW };
    const int pxx[3] = { px - 1, px, px + 1 };
    const bool vy[3] = { y > 0, true, y < 127 };
    const bool vx[3] = { px > 0, true, px < 127 };

    // A staging mapping: lane -> row-major
    const int arow = tid & (M - 1);
    const int ak4base = tid >> LOG2M;
    constexpr int ASTRIDE = 256 >> LOG2M;

    float acc[MFRAG][4][4];
#pragma unroll
    for (int mi = 0; mi < MFRAG; mi++)
#pragma unroll
        for (int ni = 0; ni < 4; ni++)
#pragma unroll
            for (int j = 0; j < 4; j++) acc[mi][ni][j] = 0.f;

    for (int chunk = 0; chunk < NCHUNK; chunk++) {
        const int kbase = chunk * 144;
        __syncthreads();   // previous compute done before overwrite

        // ---- stage A (weights): float4 -> 2 packed f16x2, conflict-free STS
#pragma unroll
        for (int it = 0; it < (A4 + 255) / 256; it++) {
            int k4 = ak4base + it * ASTRIDE;
            if ((A4 % 256 == 0) || k4 < 36) {
                float4 v = *reinterpret_cast<const float4*>(
                    wgt + (size_t)(m0 + arow) * K + kbase + k4 * 4);
                As2[(2 * k4 + 0) * APAD2 + arow] = pack_f16(v.x, v.y);
                As2[(2 * k4 + 1) * APAD2 + arow] = pack_f16(v.z, v.w);
            }
        }
        // ---- stage B (materialized im2col pairs, compile-time taps, GN in-bounds)
        {
            const int cib = chunk * 16 + khalf * 8;
            const int k2base = khalf * 36;
            float prev = 0.f;
#pragma unroll
            for (int cloc = 0; cloc < 8; cloc++) {
                const float* pc = inB + (size_t)(cib + cloc) * HWP;
                float s = 0.f, h = 0.f;
                if (GN) { s = scp[cib + cloc]; h = shp[cib + cloc]; }
#pragma unroll
                for (int t = 0; t < 9; t++) {
                    const int dy = t / 3;          // compile-time
                    const int dx = t - dy * 3;     // compile-time
                    float v = 0.f;
                    if (vy[dy] && vx[dx]) {
                        v = pc[py[dy] + pxx[dx]];
                        if (GN) v = fmaxf(fmaf(v, s, h), 0.f);
                    }
                    const int kkl = cloc * 9 + t;  // compile-time 0..71
                    if ((kkl & 1) == 0) {
                        prev = v;
                    } else {
                        Bs2[(k2base + (kkl >> 1)) * BPAD2 + px] = pack_f16(prev, v);
                    }
                }
            }
        }
        __syncthreads();

        // ---- compute: 9 k16-steps of m16n8k16
#pragma unroll
        for (int ks = 0; ks < 9; ks++) {
            const int k20 = 8 * ks + q;
            uint32_t af[MFRAG][4];
#pragma unroll
            for (int mi = 0; mi < MFRAG; mi++) {
                int row = m0w + mi * 16 + g;
                af[mi][0] = As2[k20 * APAD2 + row];
                af[mi][1] = As2[k20 * APAD2 + row + 8];
                af[mi][2] = As2[(k20 + 4) * APAD2 + row];
                af[mi][3] = As2[(k20 + 4) * APAD2 + row + 8];
            }
#pragma unroll
            for (int ni = 0; ni < 4; ni++) {
                int pxn = n0w + ni * 8 + g;
                uint32_t b0 = Bs2[k20 * BPAD2 + pxn];
                uint32_t b1 = Bs2[(k20 + 4) * BPAD2 + pxn];
#pragma unroll
                for (int mi = 0; mi < MFRAG; mi++)
                    mma_f16(acc[mi][ni], af[mi][0], af[mi][1], af[mi][2], af[mi][3], b0, b1);
            }
        }
    }

    // ---- epilogue: +bias, store NCHW as float2 pairs
#pragma unroll
    for (int mi = 0; mi < MFRAG; mi++) {
        int colo = m0 + m0w + mi * 16 + g;
        int cohi = colo + 8;
        float blo = bias[colo];
        float bhi = bias[cohi];
        float* dlo = out + (((size_t)(b * CO + colo)) * HH + y) * WW;
        float* dhi = out + (((size_t)(b * CO + cohi)) * HH + y) * WW;
#pragma unroll
        for (int ni = 0; ni < 4; ni++) {
            int x0 = n0w + ni * 8 + 2 * q;
            float2 v0 = make_float2(acc[mi][ni][0] + blo, acc[mi][ni][1] + blo);
            float2 v1 = make_float2(acc[mi][ni][2] + bhi, acc[mi][ni][3] + bhi);
            *reinterpret_cast<float2*>(dlo + x0) = v0;
            *reinterpret_cast<float2*>(dhi + x0) = v1;
        }
    }
}

// ---------------- GroupNorm statistics: partial pass ----------------
__global__ void gn_part_kernel(const float* __restrict__ x, float* __restrict__ part,
                               int Cg, int SL)
{
    const int bg = blockIdx.x / SL;
    const int sl = blockIdx.x % SL;
    const size_t n = (size_t)Cg * HWP;
    const size_t cn = n / SL;
    const float4* p = reinterpret_cast<const float4*>(x + (size_t)bg * n + (size_t)sl * cn);
    const int n4 = (int)(cn >> 2);

    float s = 0.f, ss = 0.f;
    for (int i = threadIdx.x; i < n4; i += 256) {
        float4 v = p[i];
        s  += v.x + v.y + v.z + v.w;
        ss += v.x * v.x + v.y * v.y + v.z * v.z + v.w * v.w;
    }
    __shared__ float sh_s[256], sh_ss[256];
    sh_s[threadIdx.x] = s;
    sh_ss[threadIdx.x] = ss;
    __syncthreads();
    for (int st = 128; st > 0; st >>= 1) {
        if ((int)threadIdx.x < st) {
            sh_s[threadIdx.x]  += sh_s[threadIdx.x + st];
            sh_ss[threadIdx.x] += sh_ss[threadIdx.x + st];
        }
        __syncthreads();
    }
    if (threadIdx.x == 0) {
        part[blockIdx.x * 2 + 0] = sh_s[0];
        part[blockIdx.x * 2 + 1] = sh_ss[0];
    }
}

// ---------------- GroupNorm statistics: final reduce ----------------
__global__ void gn_final_kernel(const float* __restrict__ part, float* __restrict__ mr,
                                int SL, float inv_n)
{
    const int bg = threadIdx.x;
    float s = 0.f, ss = 0.f;
    for (int i = 0; i < SL; i++) {
        s  += part[(bg * SL + i) * 2 + 0];
        ss += part[(bg * SL + i) * 2 + 1];
    }
    float mean = s * inv_n;
    float var = ss * inv_n - mean * mean;
    mr[bg * 2 + 0] = mean;
    mr[bg * 2 + 1] = rsqrtf(var + 1e-5f);
}

// ---------------- masked segment pooling (GN3+ReLU fused at read) ----------------
__global__ void pool_acc_kernel(const float* __restrict__ h, const int* __restrict__ masks,
                                const float* __restrict__ mr, const float* __restrict__ gw,
                                const float* __restrict__ gb,
                                float* __restrict__ partial, float* __restrict__ pcnt)
{
    const int b = blockIdx.y;
    const int chunk = blockIdx.x;
    const int tid = threadIdx.x;

    __shared__ float s_sums[KIDS * 65];
    __shared__ float s_cnt[KIDS];
    __shared__ float sc[64], sh[64];
    for (int i = tid; i < KIDS * 65; i += 256) s_sums[i] = 0.f;
    if (tid < KIDS) s_cnt[tid] = 0.f;
    if (tid < 64) {
        int g = tid >> 4;
        float mean = mr[(b * 4 + g) * 2 + 0];
        float rstd = mr[(b * 4 + g) * 2 + 1];
        float s = rstd * gw[tid];
        sc[tid] = s;
        sh[tid] = gb[tid] - mean * s;
    }
    __syncthreads();

    const float* hb = h + (size_t)b * 64 * HWP;
    const int* mb = masks + b * HWP;

    const int p0 = chunk * 512;
    for (int p = p0 + tid; p < p0 + 512; p += 256) {
        int k = mb[p] - 1;
        if (k >= 0) {
            atomicAdd(&s_cnt[k], 1.f);
#pragma unroll
            for (int c = 0; c < 64; c++) {
                float v = fmaxf(fmaf(hb[c * HWP + p], sc[c], sh[c]), 0.f);
                atomicAdd(&s_sums[k * 65 + c], v);
            }
        }
    }
    __syncthreads();

    float* pb = partial + (size_t)(b * 32 + chunk) * (KIDS * 64);
    for (int i = tid; i < KIDS * 64; i += 256) {
        int k = i >> 6, c = i & 63;
        pb[i] = s_sums[k * 65 + c];
    }
    if (tid < KIDS) pcnt[(b * 32 + chunk) * KIDS + tid] = s_cnt[tid];
}

// ---------------- reduce partials + dense heads ----------------
__global__ void heads_kernel(const float* __restrict__ partial, const float* __restrict__ pcnt,
                             const float* __restrict__ wb, const float* __restrict__ bb,
                             const float* __restrict__ wc, const float* __restrict__ bc,
                             float* __restrict__ out)
{
    const int b = blockIdx.x;
    const int k = blockIdx.y;
    const int c = threadIdx.x;

    float s = 0.f;
    for (int ch = 0; ch < 32; ch++)
        s += partial[(size_t)(b * 32 + ch) * (KIDS * 64) + k * 64 + c];
    float cnt = 0.f;
    for (int ch = 0; ch < 32; ch++)
        cnt += pcnt[(b * 32 + ch) * KIDS + k];
    float pooled = s / (cnt + 1e-6f);

    __shared__ float red[64];
#pragma unroll
    for (int o = 0; o < 7; o++) {
        red[c] = pooled * wb[o * 64 + c];
        __syncthreads();
        for (int st = 32; st > 0; st >>= 1) {
            if (c < st) red[c] += red[c + st];
            __syncthreads();
        }
        if (c == 0) out[(b * KIDS + k) * 7 + o] = red[0] + bb[o];
        __syncthreads();
    }
    red[c] = pooled * wc[c];
    __syncthreads();
    for (int st = 32; st > 0; st >>= 1) {
        if (c < st) red[c] += red[c + st];
        __syncthreads();
    }
    if (c == 0) {
        float z = red[0] + bc[0];
        out[BATCH * KIDS * 7 + b * KIDS + k] = 1.f / (1.f + expf(-z));
    }
}

// ---------------- launch ----------------
extern "C" void kernel_launch(void* const* d_in, const int* in_sizes, int n_in,
                              void* d_out, int out_size)
{
    const float* x    = (const float*)d_in[0];
    const int*   masks= (const int*)  d_in[1];
    const float* w1   = (const float*)d_in[2];
    const float* b1   = (const float*)d_in[3];
    const float* g1w  = (const float*)d_in[4];
    const float* g1b  = (const float*)d_in[5];
    const float* w2   = (const float*)d_in[6];
    const float* b2   = (const float*)d_in[7];
    const float* g2w  = (const float*)d_in[8];
    const float* g2b  = (const float*)d_in[9];
    const float* w3   = (const float*)d_in[10];
    const float* b3   = (const float*)d_in[11];
    const float* g3w  = (const float*)d_in[12];
    const float* g3b  = (const float*)d_in[13];
    const float* wb   = (const float*)d_in[14];
    const float* bb   = (const float*)d_in[15];
    const float* wc   = (const float*)d_in[16];
    const float* bc   = (const float*)d_in[17];
    float* out = (float*)d_out;

    float *buf1, *buf2, *buf3, *mr, *gnpart, *partial, *pcnt;
    cudaGetSymbolAddress((void**)&buf1, g_buf1);
    cudaGetSymbolAddress((void**)&buf2, g_buf2);
    cudaGetSymbolAddress((void**)&buf3, g_buf3);
    cudaGetSymbolAddress((void**)&mr, g_mr);
    cudaGetSymbolAddress((void**)&gnpart, g_gnpart);
    cudaGetSymbolAddress((void**)&partial, g_partial);
    cudaGetSymbolAddress((void**)&pcnt, g_pcnt);

    // dynamic smem: 72*APAD2*4 + 72*136*4 + GN arrays
    const int SM1 = 72 * 136 * 4 + 72 * 136 * 4;                 // 78336
    const int SM2 = 72 * 136 * 4 + 72 * 136 * 4 + 2 * 256 * 4;   // 80384
    const int SM3 = 72 * 72 * 4 + 72 * 136 * 4 + 2 * 128 * 4;    // 60928
    cudaFuncSetAttribute(conv_mma_kernel<512, 256, false>,
                         cudaFuncAttributeMaxDynamicSharedMemorySize, SM1);
    cudaFuncSetAttribute(conv_mma_kernel<256, 128, true>,
                         cudaFuncAttributeMaxDynamicSharedMemorySize, SM2);
    cudaFuncSetAttribute(conv_mma_kernel<128, 64, true>,
                         cudaFuncAttributeMaxDynamicSharedMemorySize, SM3);

    // layer 1: 512 -> 256
    conv_mma_kernel<512, 256, false><<<dim3(512, 2), 256, SM1>>>(
        x, w1, b1, buf1, nullptr, nullptr, nullptr, 0);
    gn_part_kernel<<<32 * 16, 256>>>(buf1, gnpart, 32, 16);
    gn_final_kernel<<<1, 32>>>(gnpart, mr, 16, 1.f / 524288.f);

    // layer 2: 256 -> 128 (GN1+ReLU fused into B staging)
    conv_mma_kernel<256, 128, true><<<dim3(512, 1), 256, SM2>>>(
        buf1, w2, b2, buf2, mr, g1w, g1b, 8);
    gn_part_kernel<<<16 * 32, 256>>>(buf2, gnpart, 32, 32);
    gn_final_kernel<<<1, 16>>>(gnpart, mr, 32, 1.f / 524288.f);

    // layer 3: 128 -> 64 (GN2+ReLU fused into B staging)
    conv_mma_kernel<128, 64, true><<<dim3(512, 1), 256, SM3>>>(
        buf2, w3, b3, buf3, mr, g2w, g2b, 4);
    gn_part_kernel<<<16 * 32, 256>>>(buf3, gnpart, 16, 32);
    gn_final_kernel<<<1, 16>>>(gnpart, mr, 32, 1.f / 262144.f);

    // pooling (GN3+ReLU fused at read) + heads
    pool_acc_kernel<<<dim3(32, BATCH), 256>>>(buf3, masks, mr, g3w, g3b, partial, pcnt);
    heads_kernel<<<dim3(BATCH, KIDS), 64>>>(partial, pcnt, wb, bb, wc, bc, out);
}